// round 3
// baseline (speedup 1.0000x reference)
#include <cuda_runtime.h>
#include <math.h>

#define B   32
#define NF  16
#define HW  192
#define D   256
#define S   21
#define NA  20
#define RTOT (B*NF*HW)   // 98304 rows of the input
#define MS   (B*S)       // 672 slot rows

// ---------------- device scratch (static, no allocation) ----------------
__device__ float g_xln[RTOT*D];     // LN'd input
__device__ float g_k[RTOT*D];       // keys, all frames
__device__ float g_v[RTOT*D];       // values, all frames
__device__ float g_slots[MS*D];
__device__ float g_lns[MS*D];       // LN scratch (slots / h)
__device__ float g_q[MS*D];
__device__ float g_attn[B*S*HW];    // attn_ori for current iteration
__device__ float g_upd[MS*D];
__device__ float g_gi[MS*3*D];
__device__ float g_gh[MS*3*D];
__device__ float g_h[MS*D];
__device__ float g_t[MS*D];

// ---------------- LayerNorm: one block per row, 256 threads ----------------
__global__ void __launch_bounds__(256) ln_kernel(const float* __restrict__ X,
    const float* __restrict__ g, const float* __restrict__ be,
    float* __restrict__ Y)
{
    __shared__ float sh[9];
    long row = blockIdx.x;
    int d = threadIdx.x;
    float x = X[row*D + d];

    // mean
    float v = x;
    #pragma unroll
    for (int o = 16; o; o >>= 1) v += __shfl_xor_sync(0xffffffffu, v, o);
    if ((d & 31) == 0) sh[d >> 5] = v;
    __syncthreads();
    if (d < 32) {
        float t = (d < 8) ? sh[d] : 0.f;
        #pragma unroll
        for (int o = 4; o; o >>= 1) t += __shfl_xor_sync(0xffffffffu, t, o);
        if (d == 0) sh[8] = t;
    }
    __syncthreads();
    float mean = sh[8] * (1.f / D);
    __syncthreads();

    // variance (biased)
    float c = x - mean;
    v = c * c;
    #pragma unroll
    for (int o = 16; o; o >>= 1) v += __shfl_xor_sync(0xffffffffu, v, o);
    if ((d & 31) == 0) sh[d >> 5] = v;
    __syncthreads();
    if (d < 32) {
        float t = (d < 8) ? sh[d] : 0.f;
        #pragma unroll
        for (int o = 4; o; o >>= 1) t += __shfl_xor_sync(0xffffffffu, t, o);
        if (d == 0) sh[8] = t;
    }
    __syncthreads();
    float var = sh[8] * (1.f / D);

    Y[row*D + d] = c * rsqrtf(var + 1e-5f) * g[d] + be[d];
}

// ---------------- generic C[m,n] = act(sum_k A[m,k]*W[n,k] + bias[n]) (+R) ----
// 64x64 tile, BK=16, 256 threads, 4x4 per thread. W is [N,K] row-major.
template<int RELU, int RES>
__global__ void __launch_bounds__(256) gemm_tn(const float* __restrict__ A,
    const float* __restrict__ W, const float* __restrict__ bias,
    const float* __restrict__ Rp, float* __restrict__ C, int M, int N, int K)
{
    __shared__ float As[16][65];
    __shared__ float Ws[16][65];
    int tid = threadIdx.x;
    int tx = tid & 15, ty = tid >> 4;
    int n0 = blockIdx.x * 64, m0 = blockIdx.y * 64;
    float acc[4][4];
    #pragma unroll
    for (int i = 0; i < 4; i++)
        #pragma unroll
        for (int j = 0; j < 4; j++) acc[i][j] = 0.f;

    for (int kt = 0; kt < K; kt += 16) {
        #pragma unroll
        for (int l = 0; l < 4; l++) {
            int e = tid + l*256;
            int r = e >> 4, c = e & 15;
            int m = m0 + r;
            As[c][r] = (m < M) ? A[m*K + kt + c] : 0.f;
            Ws[c][r] = W[(n0 + r)*K + kt + c];
        }
        __syncthreads();
        #pragma unroll
        for (int kk = 0; kk < 16; kk++) {
            float a[4], w[4];
            #pragma unroll
            for (int i = 0; i < 4; i++) a[i] = As[kk][ty*4 + i];
            #pragma unroll
            for (int j = 0; j < 4; j++) w[j] = Ws[kk][tx*4 + j];
            #pragma unroll
            for (int i = 0; i < 4; i++)
                #pragma unroll
                for (int j = 0; j < 4; j++)
                    acc[i][j] = fmaf(a[i], w[j], acc[i][j]);
        }
        __syncthreads();
    }
    #pragma unroll
    for (int i = 0; i < 4; i++) {
        int m = m0 + ty*4 + i;
        if (m < M) {
            #pragma unroll
            for (int j = 0; j < 4; j++) {
                int n = n0 + tx*4 + j;
                float v = acc[i][j] + bias[n];
                if (RELU) v = fmaxf(v, 0.f);
                if (RES) v += Rp[m*N + n];
                C[m*N + n] = v;
            }
        }
    }
}

// ---------------- slots0 = mu + sigma * noise ----------------
__global__ void init_slots(const float* __restrict__ noise,
    const float* __restrict__ mu, const float* __restrict__ sg,
    float* __restrict__ slots)
{
    int m = blockIdx.x, d = threadIdx.x;
    slots[m*D + d] = mu[d] + sg[d] * noise[m*D + d];
}

// ---------------- dots + softmax(slot axis) + EPS, fused ----------------
// grid (24, B), 8 warps/block; each warp owns one spatial position j.
__global__ void __launch_bounds__(256) dots_kernel(const float* __restrict__ q,
    const float* __restrict__ k, float* __restrict__ attn,
    float* __restrict__ attn_out, int f, int writeOut)
{
    __shared__ float qS[S*D];
    int b = blockIdx.y;
    for (int idx = threadIdx.x; idx < S*D; idx += 256)
        qS[idx] = q[b*S*D + idx];
    __syncthreads();

    int warp = threadIdx.x >> 5, lane = threadIdx.x & 31;
    int j = blockIdx.x * 8 + warp;
    const float* krow = k + ((long)(b*NF + f)*HW + j)*D;
    float kr[8];
    #pragma unroll
    for (int c = 0; c < 8; c++) kr[c] = krow[lane + 32*c];

    float myd = 0.f;
    for (int i = 0; i < S; i++) {
        float p = 0.f;
        #pragma unroll
        for (int c = 0; c < 8; c++) p = fmaf(qS[i*D + lane + 32*c], kr[c], p);
        #pragma unroll
        for (int o = 16; o; o >>= 1) p += __shfl_xor_sync(0xffffffffu, p, o);
        if (lane == i) myd = p;
    }
    // softmax across lanes 0..20 (slot axis), scale = D^-0.5 = 1/16
    float x = (lane < S) ? myd * 0.0625f : -1e30f;
    float mx = x;
    #pragma unroll
    for (int o = 16; o; o >>= 1) mx = fmaxf(mx, __shfl_xor_sync(0xffffffffu, mx, o));
    float e = (lane < S) ? expf(x - mx) : 0.f;
    float sum = e;
    #pragma unroll
    for (int o = 16; o; o >>= 1) sum += __shfl_xor_sync(0xffffffffu, sum, o);
    float a = e / sum + 1e-8f;
    if (lane < S) {
        attn[(b*S + lane)*HW + j] = a;
        if (writeOut)
            attn_out[((long)(b*NF + f)*S + lane)*HW + j] = a;
    }
}

// ---------------- updates = (attn_ori / rowsum) @ v : [21,192]@[192,256] ------
// grid (4, B): block = (batch b, 64-wide d chunk)
__global__ void __launch_bounds__(256) updates_kernel(const float* __restrict__ attn,
    const float* __restrict__ v, float* __restrict__ upd, int f)
{
    __shared__ float aS[S*HW];
    __shared__ float rs[S];
    __shared__ float vS[32][64];
    int b = blockIdx.y, dc = blockIdx.x;
    int tid = threadIdx.x;

    for (int idx = tid; idx < S*HW; idx += 256) aS[idx] = attn[b*S*HW + idx];
    __syncthreads();
    if (tid < S) {
        float s = 0.f;
        for (int j = 0; j < HW; j++) s += aS[tid*HW + j];
        rs[tid] = s;
    }
    __syncthreads();

    float acc[6];
    #pragma unroll
    for (int i = 0; i < 6; i++) acc[i] = 0.f;
    const float* vb = v + (long)(b*NF + f)*HW*D + dc*64;

    for (int j0 = 0; j0 < HW; j0 += 32) {
        #pragma unroll
        for (int l = 0; l < 8; l++) {
            int e = tid + l*256;
            int jj = e >> 6, dd = e & 63;
            vS[jj][dd] = vb[(j0 + jj)*D + dd];
        }
        __syncthreads();
        int oi = 0;
        for (int o = tid; o < S*64; o += 256, oi++) {
            int i = o >> 6, dd = o & 63;
            float a = 0.f;
            #pragma unroll
            for (int jj = 0; jj < 32; jj++)
                a = fmaf(aS[i*HW + j0 + jj], vS[jj][dd], a);
            acc[oi] += a;
        }
        __syncthreads();
    }
    int oi = 0;
    for (int o = tid; o < S*64; o += 256, oi++) {
        int i = o >> 6, dd = o & 63;
        upd[(b*S + i)*D + dc*64 + dd] = acc[oi] / rs[i];
    }
}

// ---------------- GRU gate combine ----------------
__global__ void gru_kernel(const float* __restrict__ gi, const float* __restrict__ gh,
                           const float* __restrict__ slots, float* __restrict__ h)
{
    int m = blockIdx.x, d = threadIdx.x;
    const float* gim = gi + m*3*D;
    const float* ghm = gh + m*3*D;
    float r = 1.f / (1.f + expf(-(gim[d]       + ghm[d])));
    float z = 1.f / (1.f + expf(-(gim[D + d]   + ghm[D + d])));
    float n = tanhf(gim[2*D + d] + r * ghm[2*D + d]);
    h[m*D + d] = (1.f - z)*n + z*slots[m*D + d];
}

// ---------------- final slots copy (first 20 of 21) ----------------
__global__ void copy_out(const float* __restrict__ slots, float* __restrict__ out)
{
    int b = blockIdx.y, s = blockIdx.x, d = threadIdx.x;
    out[(b*NA + s)*D + d] = slots[(b*S + s)*D + d];
}

// ---------------- host orchestration ----------------
extern "C" void kernel_launch(void* const* d_in, const int* in_sizes, int n_in,
                              void* d_out, int out_size)
{
    const float* inputs = (const float*)d_in[0];
    const float* noise  = (const float*)d_in[1];
    const float* mu     = (const float*)d_in[2];
    const float* sigma  = (const float*)d_in[3];
    const float* Wq  = (const float*)d_in[4];  const float* bq  = (const float*)d_in[5];
    const float* Wk  = (const float*)d_in[6];  const float* bk  = (const float*)d_in[7];
    const float* Wv  = (const float*)d_in[8];  const float* bv  = (const float*)d_in[9];
    const float* W1  = (const float*)d_in[10]; const float* b1  = (const float*)d_in[11];
    const float* W2  = (const float*)d_in[12]; const float* b2  = (const float*)d_in[13];
    const float* Wih = (const float*)d_in[14]; const float* bih = (const float*)d_in[15];
    const float* Whh = (const float*)d_in[16]; const float* bhh = (const float*)d_in[17];
    const float* gin = (const float*)d_in[18]; const float* bein = (const float*)d_in[19];
    const float* gsl = (const float*)d_in[20]; const float* besl = (const float*)d_in[21];
    const float* gff = (const float*)d_in[22]; const float* beff = (const float*)d_in[23];

    float* out = (float*)d_out;
    float* out_attn = out + (long)B*NA*D;   // attns follow slots_out

    float *xln, *kbuf, *vbuf, *slots, *lns, *q, *attn, *upd, *gi, *gh, *h, *t;
    cudaGetSymbolAddress((void**)&xln,   g_xln);
    cudaGetSymbolAddress((void**)&kbuf,  g_k);
    cudaGetSymbolAddress((void**)&vbuf,  g_v);
    cudaGetSymbolAddress((void**)&slots, g_slots);
    cudaGetSymbolAddress((void**)&lns,   g_lns);
    cudaGetSymbolAddress((void**)&q,     g_q);
    cudaGetSymbolAddress((void**)&attn,  g_attn);
    cudaGetSymbolAddress((void**)&upd,   g_upd);
    cudaGetSymbolAddress((void**)&gi,    g_gi);
    cudaGetSymbolAddress((void**)&gh,    g_gh);
    cudaGetSymbolAddress((void**)&h,     g_h);
    cudaGetSymbolAddress((void**)&t,     g_t);

    // slots0 = mu + sigma * noise
    init_slots<<<MS, D>>>(noise, mu, sigma, slots);

    // LN over all input rows, then k/v for all frames (parallel part)
    ln_kernel<<<RTOT, D>>>(inputs, gin, bein, xln);
    dim3 gBig(D/64, (RTOT + 63)/64);
    gemm_tn<0,0><<<gBig, 256>>>(xln, Wk, bk, nullptr, kbuf, RTOT, D, D);
    gemm_tn<0,0><<<gBig, 256>>>(xln, Wv, bv, nullptr, vbuf, RTOT, D, D);

    dim3 gS(D/64, (MS + 63)/64);        // 4 x 11
    dim3 gG(3*D/64, (MS + 63)/64);      // 12 x 11

    for (int f = 0; f < NF; f++) {
        for (int it = 0; it < 3; it++) {
            // q = LN(slots) @ Wq^T + bq
            ln_kernel<<<MS, D>>>(slots, gsl, besl, lns);
            gemm_tn<0,0><<<gS, 256>>>(lns, Wq, bq, nullptr, q, MS, D, D);
            // dots -> softmax over slots -> attn_ori (+ write output attn on it==2)
            dots_kernel<<<dim3(24, B), 256>>>(q, kbuf, attn, out_attn, f, it == 2);
            // normalize over spatial axis + weighted sum of v
            updates_kernel<<<dim3(4, B), 256>>>(attn, vbuf, upd, f);
            // GRU
            gemm_tn<0,0><<<gG, 256>>>(upd,   Wih, bih, nullptr, gi, MS, 3*D, D);
            gemm_tn<0,0><<<gG, 256>>>(slots, Whh, bhh, nullptr, gh, MS, 3*D, D);
            gru_kernel<<<MS, D>>>(gi, gh, slots, h);
            // MLP with residual: slots = h + relu(LN(h)@W1^T+b1)@W2^T + b2
            ln_kernel<<<MS, D>>>(h, gff, beff, lns);
            gemm_tn<1,0><<<gS, 256>>>(lns, W1, b1, nullptr, t, MS, D, D);
            gemm_tn<0,1><<<gS, 256>>>(t, W2, b2, h, slots, MS, D, D);
        }
    }
    copy_out<<<dim3(NA, B), D>>>(slots, out);
}

// round 4
// speedup vs baseline: 1.1522x; 1.1522x over previous
#include <cuda_runtime.h>
#include <math.h>

#define B   32
#define NF  16
#define HW  192
#define D   256
#define S   21
#define NA  20
#define RTOT (B*NF*HW)   // 98304
#define MS   (B*S)       // 672
#define NB   296         // persistent grid: 2 blocks/SM * 148
#define NT   256

// ---------------- device scratch ----------------
__device__ float g_xln[RTOT*D];
__device__ float g_k[RTOT*D];
__device__ float g_v[RTOT*D];
__device__ float g_slots[MS*D];
__device__ float g_q[MS*D];
__device__ float g_attn[B*S*HW];
__device__ float g_upd[MS*D];
__device__ float g_gi[MS*3*D];
__device__ float g_gh[MS*3*D];
__device__ float g_h[MS*D];
__device__ float g_t[MS*D];

__device__ unsigned g_bar_count;
__device__ volatile unsigned g_bar_gen;

struct SMem { union {
  struct { float Aln[32][257]; float Ws[32][33]; } qg;   // LN-fused 32x32 gemm
  struct { float As[32][33]; float Ws[64][33]; } gg;     // 32x64 gemm (gi/gh)
  struct { float As[32][33]; float Ws[32][33]; } pg;     // plain 32x32 gemm
  struct { float qS[S*D]; } dot;
  struct { float aS[S*HW]; float vS[32][65]; float rs[S]; } up;
} u; };

// ---------------- software grid barrier ----------------
__device__ __forceinline__ void grid_barrier(unsigned &phase)
{
    __syncthreads();
    __threadfence();
    if (threadIdx.x == 0) {
        unsigned p = phase;
        if (atomicAdd(&g_bar_count, 1u) == NB - 1u) {
            g_bar_count = 0u;
            __threadfence();
            g_bar_gen = p + 1u;
        } else {
            while (g_bar_gen <= p) __nanosleep(32);
        }
    }
    __syncthreads();
    __threadfence();   // CCTL.IVALL: invalidate L1 so fresh data is seen
    phase += 1u;
}

// ---------------- LN-fused 32x32 GEMM: C = act(LN(A) @ W^T + bias) ----------
// M=672 (21 tiles of 32), N=256 (8 tiles of 32), K=256
__device__ void stage_lngemm(const float* __restrict__ A,
    const float* __restrict__ gw, const float* __restrict__ bw,
    const float* __restrict__ W, const float* __restrict__ bias,
    float* __restrict__ C, int relu, SMem& s)
{
    int tid = threadIdx.x;
    int warp = tid >> 5, lane = tid & 31;
    int ty = tid >> 4, tx = tid & 15;
    for (int job = blockIdx.x; job < 21*8; job += NB) {
        int m0 = (job >> 3) * 32, n0 = (job & 7) * 32;
        // LN 32 rows (4 per warp) into Aln
        #pragma unroll
        for (int rr = 0; rr < 4; rr++) {
            int r = warp*4 + rr;
            const float* Ar = A + (size_t)(m0 + r) * D;
            float x[8]; float sm_ = 0.f;
            #pragma unroll
            for (int c = 0; c < 8; c++) { x[c] = Ar[lane + 32*c]; sm_ += x[c]; }
            #pragma unroll
            for (int o = 16; o; o >>= 1) sm_ += __shfl_xor_sync(~0u, sm_, o);
            float mean = sm_ * (1.f/256.f);
            float vs = 0.f;
            #pragma unroll
            for (int c = 0; c < 8; c++) { float dd = x[c]-mean; vs += dd*dd; }
            #pragma unroll
            for (int o = 16; o; o >>= 1) vs += __shfl_xor_sync(~0u, vs, o);
            float inv = rsqrtf(vs * (1.f/256.f) + 1e-5f);
            #pragma unroll
            for (int c = 0; c < 8; c++) {
                int col = lane + 32*c;
                s.u.qg.Aln[r][col] = (x[c]-mean)*inv*gw[col] + bw[col];
            }
        }
        __syncthreads();
        float a00=0.f,a01=0.f,a10=0.f,a11=0.f;
        for (int kt = 0; kt < D; kt += 32) {
            #pragma unroll
            for (int l = 0; l < 4; l++) {
                int e = tid + l*NT; int n = e >> 5, k = e & 31;
                s.u.qg.Ws[n][k] = W[(size_t)(n0+n)*D + kt + k];
            }
            __syncthreads();
            #pragma unroll
            for (int kk = 0; kk < 32; kk++) {
                float x0 = s.u.qg.Aln[ty*2][kt+kk];
                float x1 = s.u.qg.Aln[ty*2+1][kt+kk];
                float w0 = s.u.qg.Ws[tx*2][kk];
                float w1 = s.u.qg.Ws[tx*2+1][kk];
                a00 = fmaf(x0,w0,a00); a01 = fmaf(x0,w1,a01);
                a10 = fmaf(x1,w0,a10); a11 = fmaf(x1,w1,a11);
            }
            __syncthreads();
        }
        int m = m0 + ty*2, n = n0 + tx*2;
        float b0 = bias[n], b1 = bias[n+1];
        float v00=a00+b0, v01=a01+b1, v10=a10+b0, v11=a11+b1;
        if (relu) { v00=fmaxf(v00,0.f); v01=fmaxf(v01,0.f);
                    v10=fmaxf(v10,0.f); v11=fmaxf(v11,0.f); }
        C[(size_t)m*D + n]       = v00; C[(size_t)m*D + n + 1]     = v01;
        C[(size_t)(m+1)*D + n]   = v10; C[(size_t)(m+1)*D + n + 1] = v11;
    }
}

// ---------------- 32x64 GEMM tile: C[768-wide] = A @ W^T + bias ----------
__device__ __forceinline__ void gemm64_tile(const float* __restrict__ A,
    const float* __restrict__ W, const float* __restrict__ bias,
    float* __restrict__ C, int m0, int n0, SMem& s)
{
    int tid = threadIdx.x;
    int ty = tid >> 4, tx = tid & 15;
    float acc[2][4];
    #pragma unroll
    for (int i = 0; i < 2; i++)
        #pragma unroll
        for (int j = 0; j < 4; j++) acc[i][j] = 0.f;
    for (int kt = 0; kt < D; kt += 32) {
        #pragma unroll
        for (int l = 0; l < 4; l++) {
            int e = tid + l*NT; int r = e >> 5, c = e & 31;
            s.u.gg.As[c][r] = A[(size_t)(m0+r)*D + kt + c];
        }
        #pragma unroll
        for (int l = 0; l < 8; l++) {
            int e = tid + l*NT; int n = e >> 5, k = e & 31;
            s.u.gg.Ws[n][k] = W[(size_t)(n0+n)*D + kt + k];
        }
        __syncthreads();
        #pragma unroll
        for (int kk = 0; kk < 32; kk++) {
            float x0 = s.u.gg.As[kk][ty*2];
            float x1 = s.u.gg.As[kk][ty*2+1];
            float w[4];
            #pragma unroll
            for (int j = 0; j < 4; j++) w[j] = s.u.gg.Ws[tx*4+j][kk];
            #pragma unroll
            for (int j = 0; j < 4; j++) {
                acc[0][j] = fmaf(x0, w[j], acc[0][j]);
                acc[1][j] = fmaf(x1, w[j], acc[1][j]);
            }
        }
        __syncthreads();
    }
    #pragma unroll
    for (int i = 0; i < 2; i++)
        #pragma unroll
        for (int j = 0; j < 4; j++) {
            int m = m0 + ty*2 + i, n = n0 + tx*4 + j;
            C[(size_t)m*(3*D) + n] = acc[i][j] + bias[n];
        }
}

// ---------------- stage C: dots/softmax (768 jobs) + gh GEMM (252 tiles) ----
__device__ void stage_dots_gh(int f, int wout, float* __restrict__ out_attn,
    const float* __restrict__ Whh, const float* __restrict__ bhh, SMem& s)
{
    int tid = threadIdx.x;
    int warp = tid >> 5, lane = tid & 31;
    for (int job = blockIdx.x; job < 768 + 252; job += NB) {
        if (job < 768) {
            int b = job / 24, jg = job % 24;
            for (int idx = tid; idx < S*D; idx += NT)
                s.u.dot.qS[idx] = g_q[(size_t)b*S*D + idx];
            __syncthreads();
            int j = jg*8 + warp;
            const float* kr = g_k + ((size_t)(b*NF + f)*HW + j) * D;
            float kv[8];
            #pragma unroll
            for (int c = 0; c < 8; c++) kv[c] = kr[lane + 32*c];
            float myd = 0.f;
            for (int i = 0; i < S; i++) {
                float p = 0.f;
                #pragma unroll
                for (int c = 0; c < 8; c++)
                    p = fmaf(s.u.dot.qS[i*D + lane + 32*c], kv[c], p);
                #pragma unroll
                for (int o = 16; o; o >>= 1) p += __shfl_xor_sync(~0u, p, o);
                if (lane == i) myd = p;
            }
            float x = (lane < S) ? myd * 0.0625f : -1e30f;
            float mx = x;
            #pragma unroll
            for (int o = 16; o; o >>= 1) mx = fmaxf(mx, __shfl_xor_sync(~0u, mx, o));
            float e = (lane < S) ? expf(x - mx) : 0.f;
            float sum = e;
            #pragma unroll
            for (int o = 16; o; o >>= 1) sum += __shfl_xor_sync(~0u, sum, o);
            float a = e / sum + 1e-8f;
            if (lane < S) {
                g_attn[(size_t)(b*S + lane)*HW + j] = a;
                if (wout)
                    out_attn[(size_t)((b*NF + f)*S + lane)*HW + j] = a;
            }
            __syncthreads();
        } else {
            int jb = job - 768;
            gemm64_tile(g_slots, Whh, bhh, g_gh, (jb/12)*32, (jb%12)*64, s);
        }
    }
}

// ---------------- updates: attn/rowsum @ v ----------------
__device__ void stage_upd(int f, SMem& s)
{
    int tid = threadIdx.x;
    int warp = tid >> 5, lane = tid & 31;
    for (int job = blockIdx.x; job < 128; job += NB) {
        int b = job >> 2, dc = job & 3;
        for (int idx = tid; idx < S*HW; idx += NT)
            s.u.up.aS[idx] = g_attn[(size_t)b*S*HW + idx];
        __syncthreads();
        for (int r = warp; r < S; r += 8) {
            float sum = 0.f;
            #pragma unroll
            for (int c = 0; c < 6; c++) sum += s.u.up.aS[r*HW + lane + 32*c];
            #pragma unroll
            for (int o = 16; o; o >>= 1) sum += __shfl_xor_sync(~0u, sum, o);
            if (lane == 0) s.u.up.rs[r] = sum;
        }
        __syncthreads();
        float acc[6];
        #pragma unroll
        for (int i = 0; i < 6; i++) acc[i] = 0.f;
        const float* vb = g_v + (size_t)(b*NF + f)*HW*D + dc*64;
        for (int j0 = 0; j0 < HW; j0 += 32) {
            #pragma unroll
            for (int l = 0; l < 8; l++) {
                int e = tid + l*NT; int jj = e >> 6, dd = e & 63;
                s.u.up.vS[jj][dd] = vb[(size_t)(j0+jj)*D + dd];
            }
            __syncthreads();
            int oi = 0;
            for (int o = tid; o < S*64; o += NT, oi++) {
                int i = o >> 6, dd = o & 63;
                float a = 0.f;
                #pragma unroll
                for (int jj = 0; jj < 32; jj++)
                    a = fmaf(s.u.up.aS[i*HW + j0 + jj], s.u.up.vS[jj][dd], a);
                acc[oi] += a;
            }
            __syncthreads();
        }
        int oi = 0;
        for (int o = tid; o < S*64; o += NT, oi++) {
            int i = o >> 6, dd = o & 63;
            g_upd[(size_t)(b*S + i)*D + dc*64 + dd] = acc[oi] / s.u.up.rs[i];
        }
        __syncthreads();
    }
}

// ---------------- MLP2: slots = t @ W2^T + b2 + h ----------------
__device__ void stage_mlp2(const float* __restrict__ W2,
    const float* __restrict__ b2, SMem& s)
{
    int tid = threadIdx.x;
    int ty = tid >> 4, tx = tid & 15;
    for (int job = blockIdx.x; job < 21*8; job += NB) {
        int m0 = (job >> 3)*32, n0 = (job & 7)*32;
        float a00=0.f,a01=0.f,a10=0.f,a11=0.f;
        for (int kt = 0; kt < D; kt += 32) {
            #pragma unroll
            for (int l = 0; l < 4; l++) {
                int e = tid + l*NT; int r = e >> 5, c = e & 31;
                s.u.pg.As[c][r] = g_t[(size_t)(m0+r)*D + kt + c];
            }
            #pragma unroll
            for (int l = 0; l < 4; l++) {
                int e = tid + l*NT; int n = e >> 5, k = e & 31;
                s.u.pg.Ws[n][k] = W2[(size_t)(n0+n)*D + kt + k];
            }
            __syncthreads();
            #pragma unroll
            for (int kk = 0; kk < 32; kk++) {
                float x0 = s.u.pg.As[kk][ty*2];
                float x1 = s.u.pg.As[kk][ty*2+1];
                float w0 = s.u.pg.Ws[tx*2][kk];
                float w1 = s.u.pg.Ws[tx*2+1][kk];
                a00=fmaf(x0,w0,a00); a01=fmaf(x0,w1,a01);
                a10=fmaf(x1,w0,a10); a11=fmaf(x1,w1,a11);
            }
            __syncthreads();
        }
        int m = m0 + ty*2, n = n0 + tx*2;
        g_slots[(size_t)m*D+n]       = a00 + b2[n]   + g_h[(size_t)m*D+n];
        g_slots[(size_t)m*D+n+1]     = a01 + b2[n+1] + g_h[(size_t)m*D+n+1];
        g_slots[(size_t)(m+1)*D+n]   = a10 + b2[n]   + g_h[(size_t)(m+1)*D+n];
        g_slots[(size_t)(m+1)*D+n+1] = a11 + b2[n+1] + g_h[(size_t)(m+1)*D+n+1];
    }
}

// ---------------- the persistent sequential-loop kernel ----------------
__global__ void __launch_bounds__(NT, 2) slot_loop(
    const float* __restrict__ noise, const float* __restrict__ mu,
    const float* __restrict__ sg,
    const float* __restrict__ Wq,  const float* __restrict__ bq,
    const float* __restrict__ W1,  const float* __restrict__ b1,
    const float* __restrict__ W2,  const float* __restrict__ b2,
    const float* __restrict__ Wih, const float* __restrict__ bih,
    const float* __restrict__ Whh, const float* __restrict__ bhh,
    const float* __restrict__ gsl, const float* __restrict__ besl,
    const float* __restrict__ gff, const float* __restrict__ beff,
    float* __restrict__ out, float* __restrict__ out_attn)
{
    __shared__ SMem s;
    unsigned phase = 0;
    int tid = threadIdx.x;

    // slots0 = mu + sigma*noise
    for (int m = blockIdx.x; m < MS; m += NB)
        g_slots[(size_t)m*D + tid] = mu[tid] + sg[tid]*noise[(size_t)m*D + tid];
    grid_barrier(phase);

    for (int f = 0; f < NF; f++) {
        for (int it = 0; it < 3; it++) {
            // q = LN_sl(slots) @ Wq^T + bq
            stage_lngemm(g_slots, gsl, besl, Wq, bq, g_q, 0, s);
            grid_barrier(phase);
            // dots + softmax(slot axis) + eps ; gh = slots @ Whh^T + bhh
            stage_dots_gh(f, it == 2, out_attn, Whh, bhh, s);
            grid_barrier(phase);
            // updates = (attn/rowsum) @ v
            stage_upd(f, s);
            grid_barrier(phase);
            // gi = upd @ Wih^T + bih
            for (int jb = blockIdx.x; jb < 252; jb += NB)
                gemm64_tile(g_upd, Wih, bih, g_gi, (jb/12)*32, (jb%12)*64, s);
            grid_barrier(phase);
            // GRU combine
            for (int m = blockIdx.x; m < MS; m += NB) {
                const float* gim = g_gi + (size_t)m*768;
                const float* ghm = g_gh + (size_t)m*768;
                float r = 1.f/(1.f+expf(-(gim[tid]     + ghm[tid])));
                float z = 1.f/(1.f+expf(-(gim[256+tid] + ghm[256+tid])));
                float n = tanhf(gim[512+tid] + r*ghm[512+tid]);
                g_h[(size_t)m*D + tid] = (1.f - z)*n + z*g_slots[(size_t)m*D + tid];
            }
            grid_barrier(phase);
            // t = relu(LN_ff(h) @ W1^T + b1)
            stage_lngemm(g_h, gff, beff, W1, b1, g_t, 1, s);
            grid_barrier(phase);
            // slots = t @ W2^T + b2 + h
            stage_mlp2(W2, b2, s);
            grid_barrier(phase);
        }
    }
    // write slots_out (first 20 of 21 slots)
    for (int r = blockIdx.x; r < B*NA; r += NB) {
        int b = r / NA, ss = r % NA;
        out[(size_t)r*D + tid] = g_slots[(size_t)(b*S + ss)*D + tid];
    }
}

__global__ void reset_bar()
{
    g_bar_count = 0u;
    g_bar_gen = 0u;
}

// ---------------- parallel part: input LN + kv GEMMs (64x64 tiles) ---------
__global__ void __launch_bounds__(256) ln_kernel(const float* __restrict__ X,
    const float* __restrict__ g, const float* __restrict__ be,
    float* __restrict__ Y)
{
    __shared__ float sh[9];
    long row = blockIdx.x;
    int d = threadIdx.x;
    float x = X[row*D + d];
    float v = x;
    #pragma unroll
    for (int o = 16; o; o >>= 1) v += __shfl_xor_sync(0xffffffffu, v, o);
    if ((d & 31) == 0) sh[d >> 5] = v;
    __syncthreads();
    if (d < 32) {
        float t = (d < 8) ? sh[d] : 0.f;
        #pragma unroll
        for (int o = 4; o; o >>= 1) t += __shfl_xor_sync(0xffffffffu, t, o);
        if (d == 0) sh[8] = t;
    }
    __syncthreads();
    float mean = sh[8] * (1.f / D);
    __syncthreads();
    float c = x - mean;
    v = c * c;
    #pragma unroll
    for (int o = 16; o; o >>= 1) v += __shfl_xor_sync(0xffffffffu, v, o);
    if ((d & 31) == 0) sh[d >> 5] = v;
    __syncthreads();
    if (d < 32) {
        float t = (d < 8) ? sh[d] : 0.f;
        #pragma unroll
        for (int o = 4; o; o >>= 1) t += __shfl_xor_sync(0xffffffffu, t, o);
        if (d == 0) sh[8] = t;
    }
    __syncthreads();
    float var = sh[8] * (1.f / D);
    Y[row*D + d] = c * rsqrtf(var + 1e-5f) * g[d] + be[d];
}

__global__ void __launch_bounds__(256) gemm_tn(const float* __restrict__ A,
    const float* __restrict__ W, const float* __restrict__ bias,
    float* __restrict__ C, int M, int N, int K)
{
    __shared__ float As[16][65];
    __shared__ float Ws[16][65];
    int tid = threadIdx.x;
    int tx = tid & 15, ty = tid >> 4;
    int n0 = blockIdx.x * 64, m0 = blockIdx.y * 64;
    float acc[4][4];
    #pragma unroll
    for (int i = 0; i < 4; i++)
        #pragma unroll
        for (int j = 0; j < 4; j++) acc[i][j] = 0.f;
    for (int kt = 0; kt < K; kt += 16) {
        #pragma unroll
        for (int l = 0; l < 4; l++) {
            int e = tid + l*256;
            int r = e >> 4, c = e & 15;
            As[c][r] = A[(size_t)(m0 + r)*K + kt + c];
            Ws[c][r] = W[(size_t)(n0 + r)*K + kt + c];
        }
        __syncthreads();
        #pragma unroll
        for (int kk = 0; kk < 16; kk++) {
            float a[4], w[4];
            #pragma unroll
            for (int i = 0; i < 4; i++) a[i] = As[kk][ty*4 + i];
            #pragma unroll
            for (int j = 0; j < 4; j++) w[j] = Ws[kk][tx*4 + j];
            #pragma unroll
            for (int i = 0; i < 4; i++)
                #pragma unroll
                for (int j = 0; j < 4; j++)
                    acc[i][j] = fmaf(a[i], w[j], acc[i][j]);
        }
        __syncthreads();
    }
    #pragma unroll
    for (int i = 0; i < 4; i++) {
        int m = m0 + ty*4 + i;
        #pragma unroll
        for (int j = 0; j < 4; j++) {
            int n = n0 + tx*4 + j;
            C[(size_t)m*N + n] = acc[i][j] + bias[n];
        }
    }
}

// ---------------- host orchestration ----------------
extern "C" void kernel_launch(void* const* d_in, const int* in_sizes, int n_in,
                              void* d_out, int out_size)
{
    const float* inputs = (const float*)d_in[0];
    const float* noise  = (const float*)d_in[1];
    const float* mu     = (const float*)d_in[2];
    const float* sigma  = (const float*)d_in[3];
    const float* Wq  = (const float*)d_in[4];  const float* bq  = (const float*)d_in[5];
    const float* Wk  = (const float*)d_in[6];  const float* bk  = (const float*)d_in[7];
    const float* Wv  = (const float*)d_in[8];  const float* bv  = (const float*)d_in[9];
    const float* W1  = (const float*)d_in[10]; const float* b1  = (const float*)d_in[11];
    const float* W2  = (const float*)d_in[12]; const float* b2  = (const float*)d_in[13];
    const float* Wih = (const float*)d_in[14]; const float* bih = (const float*)d_in[15];
    const float* Whh = (const float*)d_in[16]; const float* bhh = (const float*)d_in[17];
    const float* gin = (const float*)d_in[18]; const float* bein = (const float*)d_in[19];
    const float* gsl = (const float*)d_in[20]; const float* besl = (const float*)d_in[21];
    const float* gff = (const float*)d_in[22]; const float* beff = (const float*)d_in[23];

    float* out = (float*)d_out;
    float* out_attn = out + (size_t)B*NA*D;

    float *xln, *kbuf, *vbuf;
    cudaGetSymbolAddress((void**)&xln,  g_xln);
    cudaGetSymbolAddress((void**)&kbuf, g_k);
    cudaGetSymbolAddress((void**)&vbuf, g_v);

    reset_bar<<<1, 1>>>();

    // parallel part: LN over all input rows, then k/v for all frames
    ln_kernel<<<RTOT, D>>>(inputs, gin, bein, xln);
    dim3 gBig(D/64, RTOT/64);
    gemm_tn<<<gBig, 256>>>(xln, Wk, bk, kbuf, RTOT, D, D);
    gemm_tn<<<gBig, 256>>>(xln, Wv, bv, vbuf, RTOT, D, D);

    // sequential part: one persistent kernel for all 16 frames x 3 iterations
    slot_loop<<<NB, NT>>>(noise, mu, sigma, Wq, bq, W1, b1, W2, b2,
                          Wih, bih, Whh, bhh, gsl, besl, gff, beff,
                          out, out_attn);
}

// round 6
// speedup vs baseline: 1.5934x; 1.3829x over previous
#include <cuda_runtime.h>
#include <math.h>

#define B   32
#define NF  16
#define HW  192
#define D   256
#define S   21
#define NA  20
#define RTOT (B*NF*HW)   // 98304
#define MS   (B*S)       // 672
#define RANKS 8

// ---------------- device scratch ----------------
__device__ float g_xln[RTOT*D];
__device__ float g_k[RTOT*D];
__device__ float g_v[RTOT*D];
__device__ float g_slots[MS*D];
__device__ float g_q[MS*D];
__device__ float g_attn[B*S*HW];
__device__ float g_upd[MS*D];
__device__ float g_h[MS*D];
__device__ float g_t[MS*D];

#define CLUSTER_SYNC() do { \
    __syncthreads(); \
    asm volatile("barrier.cluster.arrive.aligned;" ::: "memory"); \
    asm volatile("barrier.cluster.wait.aligned;"   ::: "memory"); \
} while (0)

// sA: 24 rows x 260 (padded) staging ; sW: 96 x 33 weight tile
#define SA_STRIDE 260
#define SW_STRIDE 33

// ---- LN of 21x256 rows (stride 256) into sA (24x260, pad rows zero) ----
__device__ __forceinline__ void ln_to_A(const float* __restrict__ src,
    const float* __restrict__ gam, const float* __restrict__ bet,
    float* sA, int w, int lane)
{
    __syncthreads();
    #pragma unroll
    for (int i = 0; i < 3; i++) {
        int r = w + 8*i;
        if (r < 21) {
            float x[8]; float s = 0.f;
            #pragma unroll
            for (int c = 0; c < 8; c++) { x[c] = src[(size_t)r*256 + lane + 32*c]; s += x[c]; }
            #pragma unroll
            for (int o = 16; o; o >>= 1) s += __shfl_xor_sync(~0u, s, o);
            float mean = s * (1.f/256.f);
            float vs = 0.f;
            #pragma unroll
            for (int c = 0; c < 8; c++) { float d = x[c] - mean; vs += d*d; }
            #pragma unroll
            for (int o = 16; o; o >>= 1) vs += __shfl_xor_sync(~0u, vs, o);
            float inv = rsqrtf(vs * (1.f/256.f) + 1e-5f);
            #pragma unroll
            for (int c = 0; c < 8; c++) {
                int col = lane + 32*c;
                sA[r*SA_STRIDE + col] = (x[c]-mean)*inv*gam[col] + bet[col];
            }
        } else {
            #pragma unroll
            for (int c = 0; c < 8; c++) sA[r*SA_STRIDE + lane + 32*c] = 0.f;
        }
    }
    __syncthreads();
}

// ---- plain copy of 21x256 rows into sA ----
__device__ __forceinline__ void copy_to_A(const float* __restrict__ src,
    float* sA, int w, int lane)
{
    __syncthreads();
    #pragma unroll
    for (int i = 0; i < 3; i++) {
        int r = w + 8*i;
        #pragma unroll
        for (int c = 0; c < 8; c++) {
            int col = lane + 32*c;
            sA[r*SA_STRIDE + col] = (r < 21) ? src[(size_t)r*256 + col] : 0.f;
        }
    }
    __syncthreads();
}

// ---- C[24 x NG*32] = sA[24x256] @ W^T, W rows = colb[g]+0..31, K=256 ----
// warp w owns rows {w, w+8, w+16}; lane = col within 32-group.
template<int NG>
__device__ __forceinline__ void small_gemm(const float* __restrict__ W,
    const int* colb, const float* sA, float* sW, float (&acc)[3][NG],
    int tid, int w, int lane)
{
    #pragma unroll
    for (int i = 0; i < 3; i++)
        #pragma unroll
        for (int g = 0; g < NG; g++) acc[i][g] = 0.f;
    int r0 = w, r1 = w + 8, r2 = w + 16;
    for (int kt = 0; kt < 256; kt += 32) {
        #pragma unroll
        for (int l = 0; l < NG*4; l++) {
            int e = tid + l*256;
            int n = e >> 5, k = e & 31;
            int g = n >> 5, rn = n & 31;
            sW[n*SW_STRIDE + k] = W[(size_t)(colb[g] + rn)*256 + kt + k];
        }
        __syncthreads();
        #pragma unroll
        for (int kk4 = 0; kk4 < 8; kk4++) {
            float4 a0 = *(const float4*)(sA + r0*SA_STRIDE + kt + kk4*4);
            float4 a1 = *(const float4*)(sA + r1*SA_STRIDE + kt + kk4*4);
            float4 a2 = *(const float4*)(sA + r2*SA_STRIDE + kt + kk4*4);
            #pragma unroll
            for (int g = 0; g < NG; g++) {
                const float* wp = sW + (g*32 + lane)*SW_STRIDE + kk4*4;
                float w0 = wp[0], w1 = wp[1], w2 = wp[2], w3 = wp[3];
                acc[0][g] = fmaf(a0.x,w0,fmaf(a0.y,w1,fmaf(a0.z,w2,fmaf(a0.w,w3,acc[0][g]))));
                acc[1][g] = fmaf(a1.x,w0,fmaf(a1.y,w1,fmaf(a1.z,w2,fmaf(a1.w,w3,acc[1][g]))));
                acc[2][g] = fmaf(a2.x,w0,fmaf(a2.y,w1,fmaf(a2.z,w2,fmaf(a2.w,w3,acc[2][g]))));
            }
        }
        __syncthreads();
    }
}

// ---------------- persistent per-batch cluster kernel ----------------
__global__ void __cluster_dims__(RANKS, 1, 1) __launch_bounds__(256, 2)
slot_loop(
    const float* __restrict__ noise, const float* __restrict__ mu,
    const float* __restrict__ sg,
    const float* __restrict__ Wq,  const float* __restrict__ bq,
    const float* __restrict__ W1,  const float* __restrict__ b1,
    const float* __restrict__ W2,  const float* __restrict__ b2,
    const float* __restrict__ Wih, const float* __restrict__ bih,
    const float* __restrict__ Whh, const float* __restrict__ bhh,
    const float* __restrict__ gsl, const float* __restrict__ besl,
    const float* __restrict__ gff, const float* __restrict__ beff,
    float* __restrict__ out, float* __restrict__ out_attn)
{
    __shared__ float sA[24*SA_STRIDE];   // 24.4 KB
    __shared__ float sW[96*SW_STRIDE];   // 12.4 KB

    int tid  = threadIdx.x;
    int w    = tid >> 5, lane = tid & 31;
    int rank = blockIdx.x;           // 0..7 (cluster covers full x dim)
    int b    = blockIdx.y;           // batch
    int colq = 32*rank;
    int col  = colq + lane;
    int colb1[1] = { colq };
    int colb3[3] = { colq, 256 + colq, 512 + colq };

    float* slots_b = g_slots + (size_t)b*S*256;
    float* q_b     = g_q     + (size_t)b*S*256;
    float* upd_b   = g_upd   + (size_t)b*S*256;
    float* h_b     = g_h     + (size_t)b*S*256;
    float* t_b     = g_t     + (size_t)b*S*256;
    float* attn_b  = g_attn  + (size_t)b*S*HW;

    // slots0 = mu + sigma*noise (rank writes its 32-col chunk)
    #pragma unroll
    for (int i = 0; i < 3; i++) {
        int r = w + 8*i;
        if (r < S)
            slots_b[(size_t)r*256 + col] = mu[col] + sg[col]*noise[(size_t)(b*S + r)*256 + col];
    }
    CLUSTER_SYNC();

    float gh[3][3];
    float hreg[3];

    for (int f = 0; f < NF; f++) {
        for (int it = 0; it < 3; it++) {
            // ---- S1: q = LN_sl(slots) @ Wq^T + bq (cols colq..colq+31) ----
            ln_to_A(slots_b, gsl, besl, sA, w, lane);
            {
                float acc[3][1];
                small_gemm<1>(Wq, colb1, sA, sW, acc, tid, w, lane);
                #pragma unroll
                for (int i = 0; i < 3; i++) {
                    int r = w + 8*i;
                    if (r < S) q_b[(size_t)r*256 + col] = acc[i][0] + bq[col];
                }
            }
            CLUSTER_SYNC();

            // ---- S2: dots+softmax (24 j's per rank) ; gh GEMM (regs) ----
            copy_to_A(q_b, sA, w, lane);
            #pragma unroll
            for (int jj = 0; jj < 3; jj++) {
                int j = 24*rank + w*3 + jj;
                const float* kr = g_k + ((size_t)(b*NF + f)*HW + j)*256;
                float kv[8];
                #pragma unroll
                for (int c = 0; c < 8; c++) kv[c] = kr[lane + 32*c];
                float myd = 0.f;
                for (int i = 0; i < S; i++) {
                    float p = 0.f;
                    #pragma unroll
                    for (int c = 0; c < 8; c++)
                        p = fmaf(sA[i*SA_STRIDE + lane + 32*c], kv[c], p);
                    #pragma unroll
                    for (int o = 16; o; o >>= 1) p += __shfl_xor_sync(~0u, p, o);
                    if (lane == i) myd = p;
                }
                float x = (lane < S) ? myd * 0.0625f : -1e30f;
                float mx = x;
                #pragma unroll
                for (int o = 16; o; o >>= 1) mx = fmaxf(mx, __shfl_xor_sync(~0u, mx, o));
                float e = (lane < S) ? expf(x - mx) : 0.f;
                float sum = e;
                #pragma unroll
                for (int o = 16; o; o >>= 1) sum += __shfl_xor_sync(~0u, sum, o);
                float a = e / sum + 1e-8f;
                if (lane < S) {
                    attn_b[(size_t)lane*HW + j] = a;
                    if (it == 2)
                        out_attn[(size_t)((b*NF + f)*S + lane)*HW + j] = a;
                }
            }
            // gh = slots @ Whh^T at strided gate cols {c,256+c,512+c}
            copy_to_A(slots_b, sA, w, lane);
            small_gemm<3>(Whh, colb3, sA, sW, gh, tid, w, lane);
            CLUSTER_SYNC();

            // ---- S3: updates = (attn/rowsum) @ v, 32-col chunk ----
            __syncthreads();
            for (int l = 0; l < 16; l++) {
                int e = tid + l*256;
                if (e < S*HW) sA[e] = attn_b[e];
            }
            __syncthreads();
            float rsv[3];
            #pragma unroll
            for (int i = 0; i < 3; i++) {
                int r = w + 8*i;
                if (r < S) {
                    float s = 0.f;
                    #pragma unroll
                    for (int c = 0; c < 6; c++) s += sA[r*HW + lane + 32*c];
                    #pragma unroll
                    for (int o = 16; o; o >>= 1) s += __shfl_xor_sync(~0u, s, o);
                    rsv[i] = s;
                }
            }
            float ua[3] = {0.f, 0.f, 0.f};
            int r0 = w, r1 = w + 8, r2 = w + 16;
            for (int half = 0; half < 2; half++) {
                __syncthreads();
                #pragma unroll
                for (int l = 0; l < 12; l++) {
                    int e = tid + l*256;
                    int jl = e >> 5, cl = e & 31;
                    sW[jl*SW_STRIDE + cl] =
                        g_v[((size_t)(b*NF + f)*HW + half*96 + jl)*256 + colq + cl];
                }
                __syncthreads();
                #pragma unroll 4
                for (int j = 0; j < 96; j++) {
                    float vv = sW[j*SW_STRIDE + lane];
                    ua[0] = fmaf(sA[r0*HW + half*96 + j], vv, ua[0]);
                    ua[1] = fmaf(sA[r1*HW + half*96 + j], vv, ua[1]);
                    if (r2 < S) ua[2] = fmaf(sA[r2*HW + half*96 + j], vv, ua[2]);
                }
            }
            __syncthreads();
            #pragma unroll
            for (int i = 0; i < 3; i++) {
                int r = w + 8*i;
                if (r < S) upd_b[(size_t)r*256 + col] = ua[i] / rsv[i];
            }
            CLUSTER_SYNC();

            // ---- S4: gi GEMM + GRU combine -> h ----
            copy_to_A(upd_b, sA, w, lane);
            {
                float gi[3][3];
                small_gemm<3>(Wih, colb3, sA, sW, gi, tid, w, lane);
                #pragma unroll
                for (int i = 0; i < 3; i++) {
                    int r = w + 8*i;
                    if (r < S) {
                        float irv = gi[i][0] + bih[col],       hrv = gh[i][0] + bhh[col];
                        float izv = gi[i][1] + bih[256 + col], hzv = gh[i][1] + bhh[256 + col];
                        float inv = gi[i][2] + bih[512 + col], hnv = gh[i][2] + bhh[512 + col];
                        float rr = 1.f / (1.f + expf(-(irv + hrv)));
                        float zz = 1.f / (1.f + expf(-(izv + hzv)));
                        float nn = tanhf(inv + rr*hnv);
                        float sl = slots_b[(size_t)r*256 + col];
                        float hv = (1.f - zz)*nn + zz*sl;
                        hreg[i] = hv;
                        h_b[(size_t)r*256 + col] = hv;
                    }
                }
            }
            CLUSTER_SYNC();

            // ---- S5: t = relu(LN_ff(h) @ W1^T + b1) ----
            ln_to_A(h_b, gff, beff, sA, w, lane);
            {
                float acc[3][1];
                small_gemm<1>(W1, colb1, sA, sW, acc, tid, w, lane);
                #pragma unroll
                for (int i = 0; i < 3; i++) {
                    int r = w + 8*i;
                    if (r < S) t_b[(size_t)r*256 + col] = fmaxf(acc[i][0] + b1[col], 0.f);
                }
            }
            CLUSTER_SYNC();

            // ---- S6: slots = t @ W2^T + b2 + h ----
            copy_to_A(t_b, sA, w, lane);
            {
                float acc[3][1];
                small_gemm<1>(W2, colb1, sA, sW, acc, tid, w, lane);
                #pragma unroll
                for (int i = 0; i < 3; i++) {
                    int r = w + 8*i;
                    if (r < S) slots_b[(size_t)r*256 + col] = acc[i][0] + b2[col] + hreg[i];
                }
            }
            CLUSTER_SYNC();
        }
    }

    // slots_out: first 20 slots
    #pragma unroll
    for (int i = 0; i < 3; i++) {
        int r = w + 8*i;
        if (r < NA)
            out[(size_t)(b*NA + r)*256 + col] = slots_b[(size_t)r*256 + col];
    }
}

// ---------------- parallel prepass: input LN + kv GEMMs ----------------
__global__ void __launch_bounds__(256) ln_kernel(const float* __restrict__ X,
    const float* __restrict__ g, const float* __restrict__ be,
    float* __restrict__ Y)
{
    __shared__ float sh[9];
    long row = blockIdx.x;
    int d = threadIdx.x;
    float x = X[row*D + d];
    float v = x;
    #pragma unroll
    for (int o = 16; o; o >>= 1) v += __shfl_xor_sync(0xffffffffu, v, o);
    if ((d & 31) == 0) sh[d >> 5] = v;
    __syncthreads();
    if (d < 32) {
        float t = (d < 8) ? sh[d] : 0.f;
        #pragma unroll
        for (int o = 4; o; o >>= 1) t += __shfl_xor_sync(0xffffffffu, t, o);
        if (d == 0) sh[8] = t;
    }
    __syncthreads();
    float mean = sh[8] * (1.f / D);
    __syncthreads();
    float c = x - mean;
    v = c * c;
    #pragma unroll
    for (int o = 16; o; o >>= 1) v += __shfl_xor_sync(0xffffffffu, v, o);
    if ((d & 31) == 0) sh[d >> 5] = v;
    __syncthreads();
    if (d < 32) {
        float t = (d < 8) ? sh[d] : 0.f;
        #pragma unroll
        for (int o = 4; o; o >>= 1) t += __shfl_xor_sync(0xffffffffu, t, o);
        if (d == 0) sh[8] = t;
    }
    __syncthreads();
    float var = sh[8] * (1.f / D);
    Y[row*D + d] = c * rsqrtf(var + 1e-5f) * g[d] + be[d];
}

__global__ void __launch_bounds__(256) gemm_tn(const float* __restrict__ A,
    const float* __restrict__ W, const float* __restrict__ bias,
    float* __restrict__ C, int M, int N, int K)
{
    __shared__ float As[16][65];
    __shared__ float Ws[16][65];
    int tid = threadIdx.x;
    int tx = tid & 15, ty = tid >> 4;
    int n0 = blockIdx.x * 64, m0 = blockIdx.y * 64;
    float acc[4][4];
    #pragma unroll
    for (int i = 0; i < 4; i++)
        #pragma unroll
        for (int j = 0; j < 4; j++) acc[i][j] = 0.f;
    for (int kt = 0; kt < K; kt += 16) {
        #pragma unroll
        for (int l = 0; l < 4; l++) {
            int e = tid + l*256;
            int r = e >> 4, c = e & 15;
            As[c][r] = A[(size_t)(m0 + r)*K + kt + c];
            Ws[c][r] = W[(size_t)(n0 + r)*K + kt + c];
        }
        __syncthreads();
        #pragma unroll
        for (int kk = 0; kk < 16; kk++) {
            float a[4], wv[4];
            #pragma unroll
            for (int i = 0; i < 4; i++) a[i] = As[kk][ty*4 + i];
            #pragma unroll
            for (int j = 0; j < 4; j++) wv[j] = Ws[kk][tx*4 + j];
            #pragma unroll
            for (int i = 0; i < 4; i++)
                #pragma unroll
                for (int j = 0; j < 4; j++)
                    acc[i][j] = fmaf(a[i], wv[j], acc[i][j]);
        }
        __syncthreads();
    }
    #pragma unroll
    for (int i = 0; i < 4; i++) {
        int m = m0 + ty*4 + i;
        #pragma unroll
        for (int j = 0; j < 4; j++) {
            int n = n0 + tx*4 + j;
            C[(size_t)m*N + n] = acc[i][j] + bias[n];
        }
    }
}

// ---------------- host orchestration ----------------
extern "C" void kernel_launch(void* const* d_in, const int* in_sizes, int n_in,
                              void* d_out, int out_size)
{
    const float* inputs = (const float*)d_in[0];
    const float* noise  = (const float*)d_in[1];
    const float* mu     = (const float*)d_in[2];
    const float* sigma  = (const float*)d_in[3];
    const float* Wq  = (const float*)d_in[4];  const float* bq  = (const float*)d_in[5];
    const float* Wk  = (const float*)d_in[6];  const float* bk  = (const float*)d_in[7];
    const float* Wv  = (const float*)d_in[8];  const float* bv  = (const float*)d_in[9];
    const float* W1  = (const float*)d_in[10]; const float* b1  = (const float*)d_in[11];
    const float* W2  = (const float*)d_in[12]; const float* b2  = (const float*)d_in[13];
    const float* Wih = (const float*)d_in[14]; const float* bih = (const float*)d_in[15];
    const float* Whh = (const float*)d_in[16]; const float* bhh = (const float*)d_in[17];
    const float* gin = (const float*)d_in[18]; const float* bein = (const float*)d_in[19];
    const float* gsl = (const float*)d_in[20]; const float* besl = (const float*)d_in[21];
    const float* gff = (const float*)d_in[22]; const float* beff = (const float*)d_in[23];

    float* out = (float*)d_out;
    float* out_attn = out + (size_t)B*NA*D;

    float *xln, *kbuf, *vbuf;
    cudaGetSymbolAddress((void**)&xln,  g_xln);
    cudaGetSymbolAddress((void**)&kbuf, g_k);
    cudaGetSymbolAddress((void**)&vbuf, g_v);

    // parallel prepass: LN all input rows, then k/v for all frames
    ln_kernel<<<RTOT, D>>>(inputs, gin, bein, xln);
    dim3 gBig(D/64, RTOT/64);
    gemm_tn<<<gBig, 256>>>(xln, Wk, bk, kbuf, RTOT, D, D);
    gemm_tn<<<gBig, 256>>>(xln, Wv, bv, vbuf, RTOT, D, D);

    // sequential part: one cluster (8 CTAs) per batch, fully independent
    slot_loop<<<dim3(RANKS, B), 256>>>(noise, mu, sigma, Wq, bq, W1, b1, W2, b2,
                                       Wih, bih, Whh, bhh, gsl, besl, gff, beff,
                                       out, out_attn);
}

// round 9
// speedup vs baseline: 2.3807x; 1.4941x over previous
#include <cuda_runtime.h>
#include <cuda_bf16.h>
#include <math.h>

#define B   32
#define NF  16
#define HW  192
#define D   256
#define S   21
#define NA  20
#define RTOT (B*NF*HW)   // 98304
#define MS   (B*S)       // 672
#define RANKS 8

// ---------------- device scratch ----------------
__device__ float g_xln[RTOT*D];
__device__ float g_k[RTOT*D];
__device__ float g_v[RTOT*D];
__device__ float g_slots[MS*D];
__device__ float g_q[MS*D];
__device__ float g_attn[B*S*HW];
__device__ float g_upd[MS*D];
__device__ float g_h[MS*D];
__device__ float g_t[MS*D];

#define CLUSTER_SYNC() do { \
    __syncthreads(); \
    asm volatile("barrier.cluster.arrive.aligned;" ::: "memory"); \
    asm volatile("barrier.cluster.wait.aligned;"   ::: "memory"); \
} while (0)

// ---------------- bf16 split-precision helpers ----------------
__device__ __forceinline__ void bsplit(float x, __nv_bfloat16& h, __nv_bfloat16& l)
{
    h = __float2bfloat16(x);
    l = __float2bfloat16(x - __bfloat162float(h));
}

__device__ __forceinline__ void mma_bf16(float* d, const unsigned* a, const unsigned* b)
{
    asm volatile(
        "mma.sync.aligned.m16n8k16.row.col.f32.bf16.bf16.f32 "
        "{%0,%1,%2,%3}, {%4,%5,%6,%7}, {%8,%9}, {%0,%1,%2,%3};\n"
        : "+f"(d[0]), "+f"(d[1]), "+f"(d[2]), "+f"(d[3])
        : "r"(a[0]), "r"(a[1]), "r"(a[2]), "r"(a[3]), "r"(b[0]), "r"(b[1]));
}

// ---------------- loop kernel shared-memory layout (dynamic) ----------------
#define AST 264     // bf16 stride of Ah/Al (32 rows)
#define WST 40      // bf16 stride of Wh/Wl (96 rows)
#define QST 257     // fp32 stride of staged q
#define OST 97      // fp32 stride of sOut (24 rows)
#define Y_BYTE 33792                     // 2 * 32*264*2
#define O_BYTE (Y_BYTE + 15360)          // + 2 * 96*40*2
#define LOOP_SMEM (O_BYTE + 24*OST*4)    // 58464 bytes

// ---- LN of 21 rows -> split bf16 staging (rows 21-23 zeroed) ----
__device__ __forceinline__ void ln_to_Abf(const float* __restrict__ src,
    const float* __restrict__ gam, const float* __restrict__ bet,
    __nv_bfloat16* Ah, __nv_bfloat16* Al, int w, int lane)
{
    __syncthreads();
    #pragma unroll
    for (int i = 0; i < 3; i++) {
        int r = w + 8*i;
        if (r < S) {
            float x[8]; float s = 0.f;
            #pragma unroll
            for (int c = 0; c < 8; c++) { x[c] = src[(size_t)r*256 + lane + 32*c]; s += x[c]; }
            #pragma unroll
            for (int o = 16; o; o >>= 1) s += __shfl_xor_sync(~0u, s, o);
            float mean = s * (1.f/256.f);
            float vs = 0.f;
            #pragma unroll
            for (int c = 0; c < 8; c++) { float d = x[c] - mean; vs += d*d; }
            #pragma unroll
            for (int o = 16; o; o >>= 1) vs += __shfl_xor_sync(~0u, vs, o);
            float inv = rsqrtf(vs * (1.f/256.f) + 1e-5f);
            #pragma unroll
            for (int c = 0; c < 8; c++) {
                int col = lane + 32*c;
                float y = (x[c]-mean)*inv*gam[col] + bet[col];
                __nv_bfloat16 h, l; bsplit(y, h, l);
                Ah[r*AST + col] = h; Al[r*AST + col] = l;
            }
        } else {
            #pragma unroll
            for (int c = 0; c < 8; c++) {
                int col = lane + 32*c;
                Ah[r*AST + col] = __float2bfloat16(0.f);
                Al[r*AST + col] = __float2bfloat16(0.f);
            }
        }
    }
    __syncthreads();
}

// ---- plain copy of 21 rows -> split bf16 staging ----
__device__ __forceinline__ void copy_to_Abf(const float* __restrict__ src,
    __nv_bfloat16* Ah, __nv_bfloat16* Al, int w, int lane)
{
    __syncthreads();
    #pragma unroll
    for (int i = 0; i < 3; i++) {
        int r = w + 8*i;
        #pragma unroll
        for (int c = 0; c < 8; c++) {
            int col = lane + 32*c;
            float y = (r < S) ? src[(size_t)r*256 + col] : 0.f;
            __nv_bfloat16 h, l; bsplit(y, h, l);
            Ah[r*AST + col] = h; Al[r*AST + col] = l;
        }
    }
    __syncthreads();
}

// ---- D[24 x 32*NG] = A[24x256] @ Wslice^T via bf16x3 mma; result -> sOut ----
// W rows = colb[g] + 0..31.  Warp w: m-tile mt = w>>2, n-tiles nt = (w&3)*NG + g.
template<int NG>
__device__ __forceinline__ void small_gemm_bf(const float* __restrict__ W,
    const int* colb, const __nv_bfloat16* Ah, const __nv_bfloat16* Al,
    __nv_bfloat16* Wh, __nv_bfloat16* Wl, float* sOut,
    int tid, int w, int lane)
{
    float acc[NG][4];
    #pragma unroll
    for (int g = 0; g < NG; g++)
        #pragma unroll
        for (int j = 0; j < 4; j++) acc[g][j] = 0.f;

    int mt  = w >> 2;
    int ntb = (w & 3) * NG;
    int r = lane >> 2, c = lane & 3;
    int arow = mt*16 + r;

    for (int kt = 0; kt < 256; kt += 32) {
        // stage 32NG weight rows x 32 k, split into hi/lo
        #pragma unroll
        for (int l = 0; l < NG*4; l++) {
            int e = tid + l*256;
            int n = e >> 5, k = e & 31;
            int g = n >> 5, rn = n & 31;
            float wv = W[(size_t)(colb[g] + rn)*256 + kt + k];
            __nv_bfloat16 h, lo; bsplit(wv, h, lo);
            Wh[n*WST + k] = h; Wl[n*WST + k] = lo;
        }
        __syncthreads();
        #pragma unroll
        for (int ks = 0; ks < 2; ks++) {
            int k0 = kt + ks*16;        // offset in Ah (full-K staging)
            int kw = ks*16;             // offset in Wh (chunk staging)
            unsigned ah[4], al[4];
            {
                const __nv_bfloat16* p = Ah + arow*AST + k0 + 2*c;
                ah[0] = *(const unsigned*)p;
                ah[1] = *(const unsigned*)(p + 8*AST);
                ah[2] = *(const unsigned*)(p + 8);
                ah[3] = *(const unsigned*)(p + 8*AST + 8);
                const __nv_bfloat16* q = Al + arow*AST + k0 + 2*c;
                al[0] = *(const unsigned*)q;
                al[1] = *(const unsigned*)(q + 8*AST);
                al[2] = *(const unsigned*)(q + 8);
                al[3] = *(const unsigned*)(q + 8*AST + 8);
            }
            #pragma unroll
            for (int g = 0; g < NG; g++) {
                int n = (ntb + g)*8 + r;
                const __nv_bfloat16* ph = Wh + n*WST + kw + 2*c;
                unsigned bh[2] = { *(const unsigned*)ph, *(const unsigned*)(ph + 8) };
                const __nv_bfloat16* pl = Wl + n*WST + kw + 2*c;
                unsigned bl[2] = { *(const unsigned*)pl, *(const unsigned*)(pl + 8) };
                mma_bf16(acc[g], ah, bh);
                mma_bf16(acc[g], ah, bl);
                mma_bf16(acc[g], al, bh);
            }
        }
        __syncthreads();
    }
    // write D fragments to sOut (rows >= 24 discarded)
    #pragma unroll
    for (int g = 0; g < NG; g++) {
        int row0 = mt*16 + r;
        int cc = (ntb + g)*8 + 2*c;
        sOut[row0*OST + cc]     = acc[g][0];
        sOut[row0*OST + cc + 1] = acc[g][1];
        if (mt == 0) {
            sOut[(row0+8)*OST + cc]     = acc[g][2];
            sOut[(row0+8)*OST + cc + 1] = acc[g][3];
        }
    }
    __syncthreads();
}

// ---------------- persistent per-batch cluster kernel ----------------
__global__ void __cluster_dims__(RANKS, 1, 1) __launch_bounds__(256, 2)
slot_loop(
    const float* __restrict__ noise, const float* __restrict__ mu,
    const float* __restrict__ sg,
    const float* __restrict__ Wq,  const float* __restrict__ bq,
    const float* __restrict__ W1,  const float* __restrict__ b1,
    const float* __restrict__ W2,  const float* __restrict__ b2,
    const float* __restrict__ Wih, const float* __restrict__ bih,
    const float* __restrict__ Whh, const float* __restrict__ bhh,
    const float* __restrict__ gsl, const float* __restrict__ besl,
    const float* __restrict__ gff, const float* __restrict__ beff,
    float* __restrict__ out, float* __restrict__ out_attn)
{
    extern __shared__ char sm[];
    __nv_bfloat16* Ah = (__nv_bfloat16*)sm;
    __nv_bfloat16* Al = Ah + 32*AST;
    float* sQ   = (float*)sm;                 // alias X
    float* sAtt = (float*)sm;                 // alias X
    __nv_bfloat16* Wh = (__nv_bfloat16*)(sm + Y_BYTE);
    __nv_bfloat16* Wl = Wh + 96*WST;
    float* sV   = (float*)(sm + Y_BYTE);      // alias Y (96 x 33 fp32)
    float* sOut = (float*)(sm + O_BYTE);

    int tid  = threadIdx.x;
    int w    = tid >> 5, lane = tid & 31;
    int rank = blockIdx.x;
    int b    = blockIdx.y;
    int colq = 32*rank;
    int col  = colq + lane;
    int colb1[1] = { colq };
    int colb3[3] = { colq, 256 + colq, 512 + colq };

    float* slots_b = g_slots + (size_t)b*S*256;
    float* q_b     = g_q     + (size_t)b*S*256;
    float* upd_b   = g_upd   + (size_t)b*S*256;
    float* h_b     = g_h     + (size_t)b*S*256;
    float* t_b     = g_t     + (size_t)b*S*256;
    float* attn_b  = g_attn  + (size_t)b*S*HW;

    // slots0 = mu + sigma*noise
    #pragma unroll
    for (int i = 0; i < 3; i++) {
        int r = w + 8*i;
        if (r < S)
            slots_b[(size_t)r*256 + col] = mu[col] + sg[col]*noise[(size_t)(b*S + r)*256 + col];
    }
    CLUSTER_SYNC();

    float gh[3][3];
    float hreg[3];

    for (int f = 0; f < NF; f++) {
        for (int it = 0; it < 3; it++) {
            // ---- S1: q = LN_sl(slots) @ Wq^T + bq ----
            ln_to_Abf(slots_b, gsl, besl, Ah, Al, w, lane);
            small_gemm_bf<1>(Wq, colb1, Ah, Al, Wh, Wl, sOut, tid, w, lane);
            #pragma unroll
            for (int i = 0; i < 3; i++) {
                int r = w + 8*i;
                if (r < S) q_b[(size_t)r*256 + col] = sOut[r*OST + lane] + bq[col];
            }
            CLUSTER_SYNC();

            // ---- S2: dots+softmax (24 j's per rank) ; gh GEMM ----
            __syncthreads();
            #pragma unroll
            for (int i = 0; i < 3; i++) {
                int r = w + 8*i;
                if (r < S)
                    #pragma unroll
                    for (int c = 0; c < 8; c++)
                        sQ[r*QST + lane + 32*c] = q_b[(size_t)r*256 + lane + 32*c];
            }
            __syncthreads();
            #pragma unroll
            for (int jj = 0; jj < 3; jj++) {
                int j = 24*rank + w*3 + jj;
                const float* kr = g_k + ((size_t)(b*NF + f)*HW + j)*256;
                float kv[8];
                #pragma unroll
                for (int c = 0; c < 8; c++) kv[c] = kr[lane + 32*c];
                float myd = 0.f;
                for (int i = 0; i < S; i++) {
                    float p = 0.f;
                    #pragma unroll
                    for (int c = 0; c < 8; c++)
                        p = fmaf(sQ[i*QST + lane + 32*c], kv[c], p);
                    #pragma unroll
                    for (int o = 16; o; o >>= 1) p += __shfl_xor_sync(~0u, p, o);
                    if (lane == i) myd = p;
                }
                float x = (lane < S) ? myd * 0.0625f : -1e30f;
                float mx = x;
                #pragma unroll
                for (int o = 16; o; o >>= 1) mx = fmaxf(mx, __shfl_xor_sync(~0u, mx, o));
                float e = (lane < S) ? expf(x - mx) : 0.f;
                float sum = e;
                #pragma unroll
                for (int o = 16; o; o >>= 1) sum += __shfl_xor_sync(~0u, sum, o);
                float a = e / sum + 1e-8f;
                if (lane < S) {
                    attn_b[(size_t)lane*HW + j] = a;
                    if (it == 2)
                        out_attn[(size_t)((b*NF + f)*S + lane)*HW + j] = a;
                }
            }
            // gh = slots @ Whh^T at gate cols {c, 256+c, 512+c}
            copy_to_Abf(slots_b, Ah, Al, w, lane);
            small_gemm_bf<3>(Whh, colb3, Ah, Al, Wh, Wl, sOut, tid, w, lane);
            #pragma unroll
            for (int i = 0; i < 3; i++) {
                int r = w + 8*i;
                #pragma unroll
                for (int g = 0; g < 3; g++)
                    gh[i][g] = (r < S) ? sOut[r*OST + g*32 + lane] : 0.f;
            }
            CLUSTER_SYNC();

            // ---- S3: updates = (attn/rowsum) @ v ----
            __syncthreads();
            for (int l = 0; l < 16; l++) {
                int e = tid + l*256;
                if (e < S*HW) sAtt[e] = attn_b[e];
            }
            __syncthreads();
            float rsv[3];
            #pragma unroll
            for (int i = 0; i < 3; i++) {
                int r = w + 8*i;
                if (r < S) {
                    float s = 0.f;
                    #pragma unroll
                    for (int c = 0; c < 6; c++) s += sAtt[r*HW + lane + 32*c];
                    #pragma unroll
                    for (int o = 16; o; o >>= 1) s += __shfl_xor_sync(~0u, s, o);
                    rsv[i] = s;
                }
            }
            float ua[3] = {0.f, 0.f, 0.f};
            int r0 = w, r1 = w + 8, r2 = w + 16;
            for (int half = 0; half < 2; half++) {
                __syncthreads();
                #pragma unroll
                for (int l = 0; l < 12; l++) {
                    int e = tid + l*256;
                    int jl = e >> 5, cl = e & 31;
                    sV[jl*33 + cl] =
                        g_v[((size_t)(b*NF + f)*HW + half*96 + jl)*256 + colq + cl];
                }
                __syncthreads();
                #pragma unroll 4
                for (int j = 0; j < 96; j++) {
                    float vv = sV[j*33 + lane];
                    ua[0] = fmaf(sAtt[r0*HW + half*96 + j], vv, ua[0]);
                    ua[1] = fmaf(sAtt[r1*HW + half*96 + j], vv, ua[1]);
                    if (r2 < S) ua[2] = fmaf(sAtt[r2*HW + half*96 + j], vv, ua[2]);
                }
            }
            __syncthreads();
            #pragma unroll
            for (int i = 0; i < 3; i++) {
                int r = w + 8*i;
                if (r < S) upd_b[(size_t)r*256 + col] = ua[i] / rsv[i];
            }
            CLUSTER_SYNC();

            // ---- S4: gi GEMM + GRU combine -> h ----
            copy_to_Abf(upd_b, Ah, Al, w, lane);
            small_gemm_bf<3>(Wih, colb3, Ah, Al, Wh, Wl, sOut, tid, w, lane);
            #pragma unroll
            for (int i = 0; i < 3; i++) {
                int r = w + 8*i;
                if (r < S) {
                    float irv = sOut[r*OST + lane]            + bih[col];
                    float izv = sOut[r*OST + 32 + lane]       + bih[256 + col];
                    float inv = sOut[r*OST + 64 + lane]       + bih[512 + col];
                    float hrv = gh[i][0] + bhh[col];
                    float hzv = gh[i][1] + bhh[256 + col];
                    float hnv = gh[i][2] + bhh[512 + col];
                    float rr = 1.f / (1.f + expf(-(irv + hrv)));
                    float zz = 1.f / (1.f + expf(-(izv + hzv)));
                    float nn = tanhf(inv + rr*hnv);
                    float sl = slots_b[(size_t)r*256 + col];
                    float hv = (1.f - zz)*nn + zz*sl;
                    hreg[i] = hv;
                    h_b[(size_t)r*256 + col] = hv;
                }
            }
            CLUSTER_SYNC();

            // ---- S5: t = relu(LN_ff(h) @ W1^T + b1) ----
            ln_to_Abf(h_b, gff, beff, Ah, Al, w, lane);
            small_gemm_bf<1>(W1, colb1, Ah, Al, Wh, Wl, sOut, tid, w, lane);
            #pragma unroll
            for (int i = 0; i < 3; i++) {
                int r = w + 8*i;
                if (r < S) t_b[(size_t)r*256 + col] = fmaxf(sOut[r*OST + lane] + b1[col], 0.f);
            }
            CLUSTER_SYNC();

            // ---- S6: slots = t @ W2^T + b2 + h ----
            copy_to_Abf(t_b, Ah, Al, w, lane);
            small_gemm_bf<1>(W2, colb1, Ah, Al, Wh, Wl, sOut, tid, w, lane);
            #pragma unroll
            for (int i = 0; i < 3; i++) {
                int r = w + 8*i;
                if (r < S) slots_b[(size_t)r*256 + col] = sOut[r*OST + lane] + b2[col] + hreg[i];
            }
            CLUSTER_SYNC();
        }
    }

    #pragma unroll
    for (int i = 0; i < 3; i++) {
        int r = w + 8*i;
        if (r < NA)
            out[(size_t)(b*NA + r)*256 + col] = slots_b[(size_t)r*256 + col];
    }
}

// ---------------- prepass: fused k+v GEMM via bf16x3 mma ----------------
// grid (4, 768): x = which*2 + ncta ; CTA tile 128(m) x 128(n), K=256.
__global__ void __launch_bounds__(256) kv_gemm(const float* __restrict__ A,
    const float* __restrict__ Wk, const float* __restrict__ bk, float* __restrict__ Ck,
    const float* __restrict__ Wv, const float* __restrict__ bv, float* __restrict__ Cv)
{
    __shared__ __nv_bfloat16 sAh[128*40], sAl[128*40], sWh[128*40], sWl[128*40];
    int m0 = blockIdx.y * 128;
    int which = blockIdx.x >> 1;
    int n0 = (blockIdx.x & 1) * 128;
    const float* W    = which ? Wv : Wk;
    const float* bias = which ? bv : bk;
    float* C          = which ? Cv : Ck;

    int tid = threadIdx.x;
    int w = tid >> 5, lane = tid & 31;
    int wm = w >> 1, wn = w & 1;        // warp tile 32(m) x 64(n)
    int r = lane >> 2, c = lane & 3;

    float acc[2][8][4];
    #pragma unroll
    for (int mt = 0; mt < 2; mt++)
        #pragma unroll
        for (int nt = 0; nt < 8; nt++)
            #pragma unroll
            for (int j = 0; j < 4; j++) acc[mt][nt][j] = 0.f;

    int rr = tid >> 1, kb = (tid & 1) * 16;
    for (int kt = 0; kt < 256; kt += 32) {
        #pragma unroll
        for (int q4 = 0; q4 < 4; q4++) {
            float4 av = *(const float4*)(A + (size_t)(m0 + rr)*256 + kt + kb + q4*4);
            float fa[4] = {av.x, av.y, av.z, av.w};
            float4 wv4 = *(const float4*)(W + (size_t)(n0 + rr)*256 + kt + kb + q4*4);
            float fw[4] = {wv4.x, wv4.y, wv4.z, wv4.w};
            #pragma unroll
            for (int j = 0; j < 4; j++) {
                __nv_bfloat16 h, l;
                bsplit(fa[j], h, l);
                sAh[rr*40 + kb + q4*4 + j] = h; sAl[rr*40 + kb + q4*4 + j] = l;
                bsplit(fw[j], h, l);
                sWh[rr*40 + kb + q4*4 + j] = h; sWl[rr*40 + kb + q4*4 + j] = l;
            }
        }
        __syncthreads();
        #pragma unroll
        for (int ks = 0; ks < 2; ks++) {
            int k0 = ks*16;
            unsigned ah[2][4], al[2][4];
            #pragma unroll
            for (int mt = 0; mt < 2; mt++) {
                int row = wm*32 + mt*16 + r;
                const __nv_bfloat16* p = sAh + row*40 + k0 + 2*c;
                ah[mt][0] = *(const unsigned*)p;
                ah[mt][1] = *(const unsigned*)(p + 8*40);
                ah[mt][2] = *(const unsigned*)(p + 8);
                ah[mt][3] = *(const unsigned*)(p + 8*40 + 8);
                const __nv_bfloat16* q = sAl + row*40 + k0 + 2*c;
                al[mt][0] = *(const unsigned*)q;
                al[mt][1] = *(const unsigned*)(q + 8*40);
                al[mt][2] = *(const unsigned*)(q + 8);
                al[mt][3] = *(const unsigned*)(q + 8*40 + 8);
            }
            #pragma unroll
            for (int nt = 0; nt < 8; nt++) {
                int n = wn*64 + nt*8 + r;
                const __nv_bfloat16* ph = sWh + n*40 + k0 + 2*c;
                unsigned bh[2] = { *(const unsigned*)ph, *(const unsigned*)(ph + 8) };
                const __nv_bfloat16* pl = sWl + n*40 + k0 + 2*c;
                unsigned bl[2] = { *(const unsigned*)pl, *(const unsigned*)(pl + 8) };
                #pragma unroll
                for (int mt = 0; mt < 2; mt++) {
                    mma_bf16(acc[mt][nt], ah[mt], bh);
                    mma_bf16(acc[mt][nt], ah[mt], bl);
                    mma_bf16(acc[mt][nt], al[mt], bh);
                }
            }
        }
        __syncthreads();
    }
    #pragma unroll
    for (int mt = 0; mt < 2; mt++)
        #pragma unroll
        for (int nt = 0; nt < 8; nt++) {
            int row = m0 + wm*32 + mt*16 + r;
            int cc = n0 + wn*64 + nt*8 + 2*c;
            float b0 = bias[cc], b1 = bias[cc+1];
            C[(size_t)row*256 + cc]       = acc[mt][nt][0] + b0;
            C[(size_t)row*256 + cc + 1]   = acc[mt][nt][1] + b1;
            C[(size_t)(row+8)*256 + cc]   = acc[mt][nt][2] + b0;
            C[(size_t)(row+8)*256 + cc+1] = acc[mt][nt][3] + b1;
        }
}

// ---------------- input LayerNorm ----------------
__global__ void __launch_bounds__(256) ln_kernel(const float* __restrict__ X,
    const float* __restrict__ g, const float* __restrict__ be,
    float* __restrict__ Y)
{
    __shared__ float sh[9];
    long row = blockIdx.x;
    int d = threadIdx.x;
    float x = X[row*D + d];
    float v = x;
    #pragma unroll
    for (int o = 16; o; o >>= 1) v += __shfl_xor_sync(0xffffffffu, v, o);
    if ((d & 31) == 0) sh[d >> 5] = v;
    __syncthreads();
    if (d < 32) {
        float t = (d < 8) ? sh[d] : 0.f;
        #pragma unroll
        for (int o = 4; o; o >>= 1) t += __shfl_xor_sync(0xffffffffu, t, o);
        if (d == 0) sh[8] = t;
    }
    __syncthreads();
    float mean = sh[8] * (1.f / D);
    __syncthreads();
    float c = x - mean;
    v = c * c;
    #pragma unroll
    for (int o = 16; o; o >>= 1) v += __shfl_xor_sync(0xffffffffu, v, o);
    if ((d & 31) == 0) sh[d >> 5] = v;
    __syncthreads();
    if (d < 32) {
        float t = (d < 8) ? sh[d] : 0.f;
        #pragma unroll
        for (int o = 4; o; o >>= 1) t += __shfl_xor_sync(0xffffffffu, t, o);
        if (d == 0) sh[8] = t;
    }
    __syncthreads();
    float var = sh[8] * (1.f / D);
    Y[row*D + d] = c * rsqrtf(var + 1e-5f) * g[d] + be[d];
}

// ---------------- host orchestration ----------------
extern "C" void kernel_launch(void* const* d_in, const int* in_sizes, int n_in,
                              void* d_out, int out_size)
{
    const float* inputs = (const float*)d_in[0];
    const float* noise  = (const float*)d_in[1];
    const float* mu     = (const float*)d_in[2];
    const float* sigma  = (const float*)d_in[3];
    const float* Wq  = (const float*)d_in[4];  const float* bq  = (const float*)d_in[5];
    const float* Wk  = (const float*)d_in[6];  const float* bk  = (const float*)d_in[7];
    const float* Wv  = (const float*)d_in[8];  const float* bv  = (const float*)d_in[9];
    const float* W1  = (const float*)d_in[10]; const float* b1  = (const float*)d_in[11];
    const float* W2  = (const float*)d_in[12]; const float* b2  = (const float*)d_in[13];
    const float* Wih = (const float*)d_in[14]; const float* bih = (const float*)d_in[15];
    const float* Whh = (const float*)d_in[16]; const float* bhh = (const float*)d_in[17];
    const float* gin = (const float*)d_in[18]; const float* bein = (const float*)d_in[19];
    const float* gsl = (const float*)d_in[20]; const float* besl = (const float*)d_in[21];
    const float* gff = (const float*)d_in[22]; const float* beff = (const float*)d_in[23];

    float* out = (float*)d_out;
    float* out_attn = out + (size_t)B*NA*D;

    float *xln, *kbuf, *vbuf;
    cudaGetSymbolAddress((void**)&xln,  g_xln);
    cudaGetSymbolAddress((void**)&kbuf, g_k);
    cudaGetSymbolAddress((void**)&vbuf, g_v);

    // allow >48KB dynamic smem for the loop kernel (idempotent host call)
    cudaFuncSetAttribute(slot_loop, cudaFuncAttributeMaxDynamicSharedMemorySize,
                         LOOP_SMEM);

    // parallel prepass: LN all rows, then k & v in one fused mma kernel
    ln_kernel<<<RTOT, D>>>(inputs, gin, bein, xln);
    kv_gemm<<<dim3(4, RTOT/128), 256>>>(xln, Wk, bk, kbuf, Wv, bv, vbuf);

    // sequential part: one 8-CTA cluster per batch
    slot_loop<<<dim3(RANKS, B), 256, LOOP_SMEM>>>(
        noise, mu, sigma, Wq, bq, W1, b1, W2, b2,
        Wih, bih, Whh, bhh, gsl, besl, gff, beff,
        out, out_attn);
}

// round 14
// speedup vs baseline: 2.7472x; 1.1539x over previous
#include <cuda_runtime.h>
#include <cuda_bf16.h>
#include <math.h>

#define B   32
#define NF  16
#define HW  192
#define D   256
#define S   21
#define NA  20
#define RTOT (B*NF*HW)   // 98304
#define MS   (B*S)       // 672
#define RANKS 8

// ---------------- device scratch ----------------
__device__ __nv_bfloat16 g_Ah[RTOT*D], g_Al[RTOT*D];   // split LN'd input
__device__ float g_k[RTOT*D];
__device__ float g_v[RTOT*D];
// pre-split weights
__device__ __nv_bfloat16 g_Wkh[D*D],  g_Wkl[D*D];
__device__ __nv_bfloat16 g_Wvh[D*D],  g_Wvl[D*D];
__device__ __nv_bfloat16 g_Wqh[D*D],  g_Wql[D*D];
__device__ __nv_bfloat16 g_W1h[D*D],  g_W1l[D*D];
__device__ __nv_bfloat16 g_W2h[D*D],  g_W2l[D*D];
__device__ __nv_bfloat16 g_Wihh[3*D*D], g_Wihl[3*D*D];
__device__ __nv_bfloat16 g_Whhh[3*D*D], g_Whhl[3*D*D];
// loop state
__device__ float g_slots[MS*D];
__device__ float g_q[MS*D];
__device__ float g_attn[B*S*HW];
__device__ float g_upd[MS*D];
__device__ float g_h[MS*D];
__device__ float g_t[MS*D];

#define CLUSTER_SYNC() do { \
    __syncthreads(); \
    asm volatile("barrier.cluster.arrive.aligned;" ::: "memory"); \
    asm volatile("barrier.cluster.wait.aligned;"   ::: "memory"); \
} while (0)

// ---------------- helpers ----------------
__device__ __forceinline__ void bsplit(float x, __nv_bfloat16& h, __nv_bfloat16& l)
{
    h = __float2bfloat16(x);
    l = __float2bfloat16(x - __bfloat162float(h));
}

__device__ __forceinline__ void mma_bf16(float* d, const unsigned* a, const unsigned* b)
{
    asm volatile(
        "mma.sync.aligned.m16n8k16.row.col.f32.bf16.bf16.f32 "
        "{%0,%1,%2,%3}, {%4,%5,%6,%7}, {%8,%9}, {%0,%1,%2,%3};\n"
        : "+f"(d[0]), "+f"(d[1]), "+f"(d[2]), "+f"(d[3])
        : "r"(a[0]), "r"(a[1]), "r"(a[2]), "r"(a[3]), "r"(b[0]), "r"(b[1]));
}

__device__ __forceinline__ void cp16(unsigned dst, const void* src)
{
    asm volatile("cp.async.cg.shared.global [%0], [%1], 16;\n" :: "r"(dst), "l"(src));
}
#define CP_COMMIT() asm volatile("cp.async.commit_group;\n")
#define CP_WAIT1()  asm volatile("cp.async.wait_group 1;\n" ::: "memory")
#define CP_WAIT0()  asm volatile("cp.async.wait_group 0;\n" ::: "memory")

// ---------------- loop kernel shared-memory layout (dynamic) ----------------
#define AST 264     // bf16 stride of Ah/Al (32 rows)
#define WST 40      // bf16 stride of staged weights
#define QST 257     // fp32 stride of staged q
#define OST 97      // fp32 stride of sOut
#define WOFF 33792                        // bytes: after A region (2*32*264*2)
#define OOFF (WOFF + 30720)               // after W double-buffer (2*2*96*40*2)
#define LOOP_SMEM (OOFF + 24*OST*4)       // 73824 bytes

// ---- LN of 21 rows -> split bf16 staging (rows 21-23 zeroed) ----
__device__ __forceinline__ void ln_to_Abf(const float* __restrict__ src,
    const float* __restrict__ gam, const float* __restrict__ bet,
    __nv_bfloat16* Ah, __nv_bfloat16* Al, int w, int lane)
{
    __syncthreads();
    #pragma unroll
    for (int i = 0; i < 3; i++) {
        int r = w + 8*i;
        if (r < S) {
            float x[8]; float s = 0.f;
            #pragma unroll
            for (int c = 0; c < 8; c++) { x[c] = src[(size_t)r*256 + lane + 32*c]; s += x[c]; }
            #pragma unroll
            for (int o = 16; o; o >>= 1) s += __shfl_xor_sync(~0u, s, o);
            float mean = s * (1.f/256.f);
            float vs = 0.f;
            #pragma unroll
            for (int c = 0; c < 8; c++) { float d = x[c] - mean; vs += d*d; }
            #pragma unroll
            for (int o = 16; o; o >>= 1) vs += __shfl_xor_sync(~0u, vs, o);
            float inv = rsqrtf(vs * (1.f/256.f) + 1e-5f);
            #pragma unroll
            for (int c = 0; c < 8; c++) {
                int col = lane + 32*c;
                float y = (x[c]-mean)*inv*gam[col] + bet[col];
                __nv_bfloat16 h, l; bsplit(y, h, l);
                Ah[r*AST + col] = h; Al[r*AST + col] = l;
            }
        } else {
            #pragma unroll
            for (int c = 0; c < 8; c++) {
                int col = lane + 32*c;
                Ah[r*AST + col] = __float2bfloat16(0.f);
                Al[r*AST + col] = __float2bfloat16(0.f);
            }
        }
    }
    __syncthreads();
}

__device__ __forceinline__ void copy_to_Abf(const float* __restrict__ src,
    __nv_bfloat16* Ah, __nv_bfloat16* Al, int w, int lane)
{
    __syncthreads();
    #pragma unroll
    for (int i = 0; i < 3; i++) {
        int r = w + 8*i;
        #pragma unroll
        for (int c = 0; c < 8; c++) {
            int col = lane + 32*c;
            float y = (r < S) ? src[(size_t)r*256 + col] : 0.f;
            __nv_bfloat16 h, l; bsplit(y, h, l);
            Ah[r*AST + col] = h; Al[r*AST + col] = l;
        }
    }
    __syncthreads();
}

// ---- issue cp.async for one 32-k weight chunk (hi+lo) into buffer ----
template<int NG>
__device__ __forceinline__ void issue_w(const __nv_bfloat16* __restrict__ Wh_g,
    const __nv_bfloat16* __restrict__ Wl_g, const int* colb, int kt,
    unsigned wbase, int buf, int tid)
{
    const int half = 128*NG;
    #pragma unroll
    for (int l = 0; l < NG; l++) {
        int e = tid + l*256;
        int arr = (e < half) ? 0 : 1;
        int x = (e < half) ? e : e - half;
        int n = x >> 2, q = x & 3;
        int g = n >> 5, rn = n & 31;
        const __nv_bfloat16* src =
            (arr ? Wl_g : Wh_g) + (size_t)(colb[g] + rn)*256 + kt + q*8;
        unsigned dst = wbase + (unsigned)(buf*7680 + arr*3840 + n*WST + q*8)*2;
        cp16(dst, src);
    }
    CP_COMMIT();
}

// ---- D[24 x 32*NG] = A[24x256] @ Wslice^T via bf16x3 mma; result -> sOut ----
template<int NG>
__device__ __forceinline__ void small_gemm_bf(const __nv_bfloat16* __restrict__ Wh_g,
    const __nv_bfloat16* __restrict__ Wl_g, const int* colb,
    const __nv_bfloat16* Ah, const __nv_bfloat16* Al,
    __nv_bfloat16* Wsm, unsigned wbase, float* sOut,
    int tid, int w, int lane)
{
    float acc[NG][4];
    #pragma unroll
    for (int g = 0; g < NG; g++)
        #pragma unroll
        for (int j = 0; j < 4; j++) acc[g][j] = 0.f;

    int mt  = w >> 2;
    int ntb = (w & 3) * NG;
    int r = lane >> 2, c = lane & 3;
    int arow = mt*16 + r;

    issue_w<NG>(Wh_g, Wl_g, colb, 0, wbase, 0, tid);

    #pragma unroll
    for (int c8 = 0; c8 < 8; c8++) {
        if (c8 < 7) {
            issue_w<NG>(Wh_g, Wl_g, colb, (c8+1)*32, wbase, (c8+1)&1, tid);
            CP_WAIT1();
        } else {
            CP_WAIT0();
        }
        __syncthreads();
        const __nv_bfloat16* Wh_s = Wsm + (c8&1)*7680;
        const __nv_bfloat16* Wl_s = Wh_s + 3840;
        #pragma unroll
        for (int ks = 0; ks < 2; ks++) {
            int k0 = c8*32 + ks*16;   // offset in Ah (full-K staging)
            int kw = ks*16;           // offset in W chunk
            unsigned ah[4], al[4];
            {
                const __nv_bfloat16* p = Ah + arow*AST + k0 + 2*c;
                ah[0] = *(const unsigned*)p;
                ah[1] = *(const unsigned*)(p + 8*AST);
                ah[2] = *(const unsigned*)(p + 8);
                ah[3] = *(const unsigned*)(p + 8*AST + 8);
                const __nv_bfloat16* q = Al + arow*AST + k0 + 2*c;
                al[0] = *(const unsigned*)q;
                al[1] = *(const unsigned*)(q + 8*AST);
                al[2] = *(const unsigned*)(q + 8);
                al[3] = *(const unsigned*)(q + 8*AST + 8);
            }
            #pragma unroll
            for (int g = 0; g < NG; g++) {
                int n = (ntb + g)*8 + r;
                const __nv_bfloat16* ph = Wh_s + n*WST + kw + 2*c;
                unsigned bh[2] = { *(const unsigned*)ph, *(const unsigned*)(ph + 8) };
                const __nv_bfloat16* pl = Wl_s + n*WST + kw + 2*c;
                unsigned bl[2] = { *(const unsigned*)pl, *(const unsigned*)(pl + 8) };
                mma_bf16(acc[g], ah, bh);
                mma_bf16(acc[g], ah, bl);
                mma_bf16(acc[g], al, bh);
            }
        }
        __syncthreads();
    }
    #pragma unroll
    for (int g = 0; g < NG; g++) {
        int row0 = mt*16 + r;
        int cc = (ntb + g)*8 + 2*c;
        sOut[row0*OST + cc]     = acc[g][0];
        sOut[row0*OST + cc + 1] = acc[g][1];
        if (mt == 0) {
            sOut[(row0+8)*OST + cc]     = acc[g][2];
            sOut[(row0+8)*OST + cc + 1] = acc[g][3];
        }
    }
    __syncthreads();
}

// ---------------- persistent per-batch cluster kernel ----------------
__global__ void __cluster_dims__(RANKS, 1, 1) __launch_bounds__(256, 2)
slot_loop(
    const float* __restrict__ noise, const float* __restrict__ mu,
    const float* __restrict__ sg,
    const float* __restrict__ bq,  const float* __restrict__ b1,
    const float* __restrict__ b2,
    const float* __restrict__ bih, const float* __restrict__ bhh,
    const float* __restrict__ gsl, const float* __restrict__ besl,
    const float* __restrict__ gff, const float* __restrict__ beff,
    float* __restrict__ out, float* __restrict__ out_attn)
{
    extern __shared__ char sm[];
    __nv_bfloat16* Ah = (__nv_bfloat16*)sm;
    __nv_bfloat16* Al = Ah + 32*AST;
    float* sQ   = (float*)sm;                 // alias A region
    float* sAtt = (float*)sm;                 // alias A region
    __nv_bfloat16* Wsm = (__nv_bfloat16*)(sm + WOFF);
    float* sV   = (float*)(sm + WOFF);        // alias W region (96 x 33 fp32)
    float* sOut = (float*)(sm + OOFF);
    unsigned wbase = (unsigned)__cvta_generic_to_shared(Wsm);

    int tid  = threadIdx.x;
    int w    = tid >> 5, lane = tid & 31;
    int rank = blockIdx.x;
    int b    = blockIdx.y;
    int colq = 32*rank;
    int col  = colq + lane;
    int colb1[1] = { colq };
    int colb3[3] = { colq, 256 + colq, 512 + colq };

    float* slots_b = g_slots + (size_t)b*S*256;
    float* q_b     = g_q     + (size_t)b*S*256;
    float* upd_b   = g_upd   + (size_t)b*S*256;
    float* h_b     = g_h     + (size_t)b*S*256;
    float* t_b     = g_t     + (size_t)b*S*256;
    float* attn_b  = g_attn  + (size_t)b*S*HW;

    // slots0 = mu + sigma*noise
    #pragma unroll
    for (int i = 0; i < 3; i++) {
        int r = w + 8*i;
        if (r < S)
            slots_b[(size_t)r*256 + col] = mu[col] + sg[col]*noise[(size_t)(b*S + r)*256 + col];
    }
    CLUSTER_SYNC();

    float gh[3][3];
    float hreg[3];

    for (int f = 0; f < NF; f++) {
        for (int it = 0; it < 3; it++) {
            // ---- S1: q = LN_sl(slots) @ Wq^T + bq ----
            ln_to_Abf(slots_b, gsl, besl, Ah, Al, w, lane);
            small_gemm_bf<1>(g_Wqh, g_Wql, colb1, Ah, Al, Wsm, wbase, sOut, tid, w, lane);
            #pragma unroll
            for (int i = 0; i < 3; i++) {
                int r = w + 8*i;
                if (r < S) q_b[(size_t)r*256 + col] = sOut[r*OST + lane] + bq[col];
            }
            CLUSTER_SYNC();

            // ---- S2: dots+softmax (24 j's per rank) ; gh GEMM ----
            __syncthreads();
            #pragma unroll
            for (int i = 0; i < 3; i++) {
                int r = w + 8*i;
                if (r < S)
                    #pragma unroll
                    for (int c = 0; c < 8; c++)
                        sQ[r*QST + lane + 32*c] = q_b[(size_t)r*256 + lane + 32*c];
            }
            __syncthreads();
            #pragma unroll
            for (int jj = 0; jj < 3; jj++) {
                int j = 24*rank + w*3 + jj;
                const float* kr = g_k + ((size_t)(b*NF + f)*HW + j)*256;
                float kv[8];
                #pragma unroll
                for (int c = 0; c < 8; c++) kv[c] = kr[lane + 32*c];
                float myd = 0.f;
                #pragma unroll
                for (int i = 0; i < S; i++) {
                    float p = 0.f;
                    #pragma unroll
                    for (int c = 0; c < 8; c++)
                        p = fmaf(sQ[i*QST + lane + 32*c], kv[c], p);
                    #pragma unroll
                    for (int o = 16; o; o >>= 1) p += __shfl_xor_sync(~0u, p, o);
                    if (lane == i) myd = p;
                }
                float x = (lane < S) ? myd * 0.0625f : -1e30f;
                float mx = x;
                #pragma unroll
                for (int o = 16; o; o >>= 1) mx = fmaxf(mx, __shfl_xor_sync(~0u, mx, o));
                float e = (lane < S) ? expf(x - mx) : 0.f;
                float sum = e;
                #pragma unroll
                for (int o = 16; o; o >>= 1) sum += __shfl_xor_sync(~0u, sum, o);
                float a = e / sum + 1e-8f;
                if (lane < S) {
                    attn_b[(size_t)lane*HW + j] = a;
                    if (it == 2)
                        out_attn[(size_t)((b*NF + f)*S + lane)*HW + j] = a;
                }
            }
            // gh = slots @ Whh^T at gate cols {c, 256+c, 512+c}
            copy_to_Abf(slots_b, Ah, Al, w, lane);
            small_gemm_bf<3>(g_Whhh, g_Whhl, colb3, Ah, Al, Wsm, wbase, sOut, tid, w, lane);
            #pragma unroll
            for (int i = 0; i < 3; i++) {
                int r = w + 8*i;
                #pragma unroll
                for (int g = 0; g < 3; g++)
                    gh[i][g] = (r < S) ? sOut[r*OST + g*32 + lane] : 0.f;
            }
            CLUSTER_SYNC();

            // ---- S3: updates = (attn/rowsum) @ v ----
            __syncthreads();
            for (int l = 0; l < 16; l++) {
                int e = tid + l*256;
                if (e < S*HW) sAtt[e] = attn_b[e];
            }
            __syncthreads();
            float rsv[3];
            #pragma unroll
            for (int i = 0; i < 3; i++) {
                int r = w + 8*i;
                if (r < S) {
                    float s = 0.f;
                    #pragma unroll
                    for (int c = 0; c < 6; c++) s += sAtt[r*HW + lane + 32*c];
                    #pragma unroll
                    for (int o = 16; o; o >>= 1) s += __shfl_xor_sync(~0u, s, o);
                    rsv[i] = s;
                }
            }
            float ua[3] = {0.f, 0.f, 0.f};
            int r0 = w, r1 = w + 8, r2 = w + 16;
            for (int half = 0; half < 2; half++) {
                __syncthreads();
                #pragma unroll
                for (int l = 0; l < 12; l++) {
                    int e = tid + l*256;
                    int jl = e >> 5, cl = e & 31;
                    sV[jl*33 + cl] =
                        g_v[((size_t)(b*NF + f)*HW + half*96 + jl)*256 + colq + cl];
                }
                __syncthreads();
                #pragma unroll 4
                for (int j = 0; j < 96; j++) {
                    float vv = sV[j*33 + lane];
                    ua[0] = fmaf(sAtt[r0*HW + half*96 + j], vv, ua[0]);
                    ua[1] = fmaf(sAtt[r1*HW + half*96 + j], vv, ua[1]);
                    if (r2 < S) ua[2] = fmaf(sAtt[r2*HW + half*96 + j], vv, ua[2]);
                }
            }
            __syncthreads();
            #pragma unroll
            for (int i = 0; i < 3; i++) {
                int r = w + 8*i;
                if (r < S) upd_b[(size_t)r*256 + col] = ua[i] / rsv[i];
            }
            CLUSTER_SYNC();

            // ---- S4: gi GEMM + GRU combine -> h ----
            copy_to_Abf(upd_b, Ah, Al, w, lane);
            small_gemm_bf<3>(g_Wihh, g_Wihl, colb3, Ah, Al, Wsm, wbase, sOut, tid, w, lane);
            #pragma unroll
            for (int i = 0; i < 3; i++) {
                int r = w + 8*i;
                if (r < S) {
                    float irv = sOut[r*OST + lane]      + bih[col];
                    float izv = sOut[r*OST + 32 + lane] + bih[256 + col];
                    float inv = sOut[r*OST + 64 + lane] + bih[512 + col];
                    float hrv = gh[i][0] + bhh[col];
                    float hzv = gh[i][1] + bhh[256 + col];
                    float hnv = gh[i][2] + bhh[512 + col];
                    float rr = 1.f / (1.f + expf(-(irv + hrv)));
                    float zz = 1.f / (1.f + expf(-(izv + hzv)));
                    float nn = tanhf(inv + rr*hnv);
                    float sl = slots_b[(size_t)r*256 + col];
                    float hv = (1.f - zz)*nn + zz*sl;
                    hreg[i] = hv;
                    h_b[(size_t)r*256 + col] = hv;
                }
            }
            CLUSTER_SYNC();

            // ---- S5: t = relu(LN_ff(h) @ W1^T + b1) ----
            ln_to_Abf(h_b, gff, beff, Ah, Al, w, lane);
            small_gemm_bf<1>(g_W1h, g_W1l, colb1, Ah, Al, Wsm, wbase, sOut, tid, w, lane);
            #pragma unroll
            for (int i = 0; i < 3; i++) {
                int r = w + 8*i;
                if (r < S) t_b[(size_t)r*256 + col] = fmaxf(sOut[r*OST + lane] + b1[col], 0.f);
            }
            CLUSTER_SYNC();

            // ---- S6: slots = t @ W2^T + b2 + h ----
            copy_to_Abf(t_b, Ah, Al, w, lane);
            small_gemm_bf<1>(g_W2h, g_W2l, colb1, Ah, Al, Wsm, wbase, sOut, tid, w, lane);
            #pragma unroll
            for (int i = 0; i < 3; i++) {
                int r = w + 8*i;
                if (r < S) slots_b[(size_t)r*256 + col] = sOut[r*OST + lane] + b2[col] + hreg[i];
            }
            CLUSTER_SYNC();
        }
    }

    #pragma unroll
    for (int i = 0; i < 3; i++) {
        int r = w + 8*i;
        if (r < NA)
            out[(size_t)(b*NA + r)*256 + col] = slots_b[(size_t)r*256 + col];
    }
}

// ---------------- prepass: fused k+v GEMM, pre-split operands, cp.async ----
// grid (4, 768): which = bx>>1, n0 = (bx&1)*128 ; CTA tile 128m x 128n, K=256.
#define KVA 5120     // elems per staged array (128 x 40)
#define KVB 20480    // elems per buffer (4 arrays)
__global__ void __launch_bounds__(256) kv_gemm(
    const float* __restrict__ bk, float* __restrict__ Ck,
    const float* __restrict__ bv, float* __restrict__ Cv)
{
    extern __shared__ __nv_bfloat16 smkv[];
    unsigned sbase = (unsigned)__cvta_generic_to_shared(smkv);

    int m0 = blockIdx.y * 128;
    int which = blockIdx.x >> 1;
    int n0 = (blockIdx.x & 1) * 128;
    const __nv_bfloat16* Wh_g = which ? g_Wvh : g_Wkh;
    const __nv_bfloat16* Wl_g = which ? g_Wvl : g_Wkl;
    const float* bias = which ? bv : bk;
    float* C          = which ? Cv : Ck;

    int tid = threadIdx.x;
    int w = tid >> 5, lane = tid & 31;
    int wm = w >> 1, wn = w & 1;
    int r = lane >> 2, c = lane & 3;

    float acc[2][8][4];
    #pragma unroll
    for (int mt = 0; mt < 2; mt++)
        #pragma unroll
        for (int nt = 0; nt < 8; nt++)
            #pragma unroll
            for (int j = 0; j < 4; j++) acc[mt][nt][j] = 0.f;

    // issue one 32-k chunk: 4 arrays (Ah, Al, Wh, Wl) x 128 rows x 32 k
    auto issue = [&](int kt, int buf) {
        #pragma unroll
        for (int l = 0; l < 8; l++) {
            int e = tid + l*256;
            int arr = e >> 9, x = e & 511;
            int row = x >> 2, q = x & 3;
            const __nv_bfloat16* src;
            switch (arr) {
                case 0: src = g_Ah + (size_t)(m0 + row)*256 + kt + q*8; break;
                case 1: src = g_Al + (size_t)(m0 + row)*256 + kt + q*8; break;
                case 2: src = Wh_g + (size_t)(n0 + row)*256 + kt + q*8; break;
                default:src = Wl_g + (size_t)(n0 + row)*256 + kt + q*8; break;
            }
            unsigned dst = sbase + (unsigned)(buf*KVB + arr*KVA + row*40 + q*8)*2;
            cp16(dst, src);
        }
        CP_COMMIT();
    };

    issue(0, 0);
    #pragma unroll
    for (int c8 = 0; c8 < 8; c8++) {
        if (c8 < 7) { issue((c8+1)*32, (c8+1)&1); CP_WAIT1(); }
        else        { CP_WAIT0(); }
        __syncthreads();
        const __nv_bfloat16* sAh = smkv + (c8&1)*KVB;
        const __nv_bfloat16* sAl = sAh + KVA;
        const __nv_bfloat16* sWh = sAh + 2*KVA;
        const __nv_bfloat16* sWl = sAh + 3*KVA;
        #pragma unroll
        for (int ks = 0; ks < 2; ks++) {
            int k0 = ks*16;
            unsigned ah[2][4], al[2][4];
            #pragma unroll
            for (int mt = 0; mt < 2; mt++) {
                int row = wm*32 + mt*16 + r;
                const __nv_bfloat16* p = sAh + row*40 + k0 + 2*c;
                ah[mt][0] = *(const unsigned*)p;
                ah[mt][1] = *(const unsigned*)(p + 8*40);
                ah[mt][2] = *(const unsigned*)(p + 8);
                ah[mt][3] = *(const unsigned*)(p + 8*40 + 8);
                const __nv_bfloat16* q = sAl + row*40 + k0 + 2*c;
                al[mt][0] = *(const unsigned*)q;
                al[mt][1] = *(const unsigned*)(q + 8*40);
                al[mt][2] = *(const unsigned*)(q + 8);
                al[mt][3] = *(const unsigned*)(q + 8*40 + 8);
            }
            #pragma unroll
            for (int nt = 0; nt < 8; nt++) {
                int n = wn*64 + nt*8 + r;
                const __nv_bfloat16* ph = sWh + n*40 + k0 + 2*c;
                unsigned bh[2] = { *(const unsigned*)ph, *(const unsigned*)(ph + 8) };
                const __nv_bfloat16* pl = sWl + n*40 + k0 + 2*c;
                unsigned bl[2] = { *(const unsigned*)pl, *(const unsigned*)(pl + 8) };
                #pragma unroll
                for (int mt = 0; mt < 2; mt++) {
                    mma_bf16(acc[mt][nt], ah[mt], bh);
                    mma_bf16(acc[mt][nt], ah[mt], bl);
                    mma_bf16(acc[mt][nt], al[mt], bh);
                }
            }
        }
        __syncthreads();
    }
    #pragma unroll
    for (int mt = 0; mt < 2; mt++)
        #pragma unroll
        for (int nt = 0; nt < 8; nt++) {
            int row = m0 + wm*32 + mt*16 + r;
            int cc = n0 + wn*64 + nt*8 + 2*c;
            float b0 = bias[cc], b1 = bias[cc+1];
            C[(size_t)row*256 + cc]       = acc[mt][nt][0] + b0;
            C[(size_t)row*256 + cc + 1]   = acc[mt][nt][1] + b1;
            C[(size_t)(row+8)*256 + cc]   = acc[mt][nt][2] + b0;
            C[(size_t)(row+8)*256 + cc+1] = acc[mt][nt][3] + b1;
        }
}

// ---------------- input LayerNorm: warp per row, emit split bf16 ----------
__global__ void __launch_bounds__(256) ln_kernel(const float* __restrict__ X,
    const float* __restrict__ g, const float* __restrict__ be)
{
    int w = threadIdx.x >> 5, lane = threadIdx.x & 31;
    size_t row = (size_t)blockIdx.x*8 + w;
    const float* Xr = X + row*256;
    float x[8]; float s = 0.f;
    #pragma unroll
    for (int c = 0; c < 8; c++) { x[c] = Xr[lane + 32*c]; s += x[c]; }
    #pragma unroll
    for (int o = 16; o; o >>= 1) s += __shfl_xor_sync(~0u, s, o);
    float mean = s * (1.f/256.f);
    float vs = 0.f;
    #pragma unroll
    for (int c = 0; c < 8; c++) { float d = x[c] - mean; vs += d*d; }
    #pragma unroll
    for (int o = 16; o; o >>= 1) vs += __shfl_xor_sync(~0u, vs, o);
    float inv = rsqrtf(vs * (1.f/256.f) + 1e-5f);
    #pragma unroll
    for (int c = 0; c < 8; c++) {
        int col = lane + 32*c;
        float y = (x[c]-mean)*inv*g[col] + be[col];
        __nv_bfloat16 h, l; bsplit(y, h, l);
        g_Ah[row*256 + col] = h;
        g_Al[row*256 + col] = l;
    }
}

// ---------------- weight split conversion ----------------
__global__ void conv_split(const float* __restrict__ W,
    __nv_bfloat16* __restrict__ Hp, __nv_bfloat16* __restrict__ Lp, int n)
{
    int i = blockIdx.x*256 + threadIdx.x;
    if (i < n) {
        __nv_bfloat16 h, l; bsplit(W[i], h, l);
        Hp[i] = h; Lp[i] = l;
    }
}

// ---------------- host orchestration ----------------
extern "C" void kernel_launch(void* const* d_in, const int* in_sizes, int n_in,
                              void* d_out, int out_size)
{
    const float* inputs = (const float*)d_in[0];
    const float* noise  = (const float*)d_in[1];
    const float* mu     = (const float*)d_in[2];
    const float* sigma  = (const float*)d_in[3];
    const float* Wq  = (const float*)d_in[4];  const float* bq  = (const float*)d_in[5];
    const float* Wk  = (const float*)d_in[6];  const float* bk  = (const float*)d_in[7];
    const float* Wv  = (const float*)d_in[8];  const float* bv  = (const float*)d_in[9];
    const float* W1  = (const float*)d_in[10]; const float* b1  = (const float*)d_in[11];
    const float* W2  = (const float*)d_in[12]; const float* b2  = (const float*)d_in[13];
    const float* Wih = (const float*)d_in[14]; const float* bih = (const float*)d_in[15];
    const float* Whh = (const float*)d_in[16]; const float* bhh = (const float*)d_in[17];
    const float* gin = (const float*)d_in[18]; const float* bein = (const float*)d_in[19];
    const float* gsl = (const float*)d_in[20]; const float* besl = (const float*)d_in[21];
    const float* gff = (const float*)d_in[22]; const float* beff = (const float*)d_in[23];

    float* out = (float*)d_out;
    float* out_attn = out + (size_t)B*NA*D;

    float *kbuf, *vbuf;
    cudaGetSymbolAddress((void**)&kbuf, g_k);
    cudaGetSymbolAddress((void**)&vbuf, g_v);
    __nv_bfloat16 *wkh,*wkl,*wvh,*wvl,*wqh,*wql,*w1h,*w1l,*w2h,*w2l,*wihh,*wihl,*whhh,*whhl;
    cudaGetSymbolAddress((void**)&wkh, g_Wkh);  cudaGetSymbolAddress((void**)&wkl, g_Wkl);
    cudaGetSymbolAddress((void**)&wvh, g_Wvh);  cudaGetSymbolAddress((void**)&wvl, g_Wvl);
    cudaGetSymbolAddress((void**)&wqh, g_Wqh);  cudaGetSymbolAddress((void**)&wql, g_Wql);
    cudaGetSymbolAddress((void**)&w1h, g_W1h);  cudaGetSymbolAddress((void**)&w1l, g_W1l);
    cudaGetSymbolAddress((void**)&w2h, g_W2h);  cudaGetSymbolAddress((void**)&w2l, g_W2l);
    cudaGetSymbolAddress((void**)&wihh, g_Wihh); cudaGetSymbolAddress((void**)&wihl, g_Wihl);
    cudaGetSymbolAddress((void**)&whhh, g_Whhh); cudaGetSymbolAddress((void**)&whhl, g_Whhl);

    cudaFuncSetAttribute(slot_loop, cudaFuncAttributeMaxDynamicSharedMemorySize, LOOP_SMEM);
    cudaFuncSetAttribute(kv_gemm,   cudaFuncAttributeMaxDynamicSharedMemorySize, 2*KVB*2);

    // weight splits (tiny)
    conv_split<<<256, 256>>>(Wk,  wkh,  wkl,  D*D);
    conv_split<<<256, 256>>>(Wv,  wvh,  wvl,  D*D);
    conv_split<<<256, 256>>>(Wq,  wqh,  wql,  D*D);
    conv_split<<<256, 256>>>(W1,  w1h,  w1l,  D*D);
    conv_split<<<256, 256>>>(W2,  w2h,  w2l,  D*D);
    conv_split<<<768, 256>>>(Wih, wihh, wihl, 3*D*D);
    conv_split<<<768, 256>>>(Whh, whhh, whhl, 3*D*D);

    // LN all input rows -> split bf16 A
    ln_kernel<<<RTOT/8, 256>>>(inputs, gin, bein);

    // k & v for all frames
    kv_gemm<<<dim3(4, RTOT/128), 256, 2*KVB*2>>>(bk, kbuf, bv, vbuf);

    // sequential part: one 8-CTA cluster per batch
    slot_loop<<<dim3(RANKS, B), 256, LOOP_SMEM>>>(
        noise, mu, sigma, bq, b1, b2, bih, bhh,
        gsl, besl, gff, beff, out, out_attn);
}

// round 15
// speedup vs baseline: 2.7488x; 1.0006x over previous
#include <cuda_runtime.h>
#include <cuda_bf16.h>
#include <math.h>

#define B   32
#define NF  16
#define HW  192
#define D   256
#define S   21
#define NA  20
#define RTOT (B*NF*HW)   // 98304
#define MS   (B*S)       // 672
#define RANKS 8

// ---------------- device scratch ----------------
__device__ __nv_bfloat16 g_Ah[RTOT*D], g_Al[RTOT*D];   // split LN'd input
__device__ float g_k[RTOT*D];
__device__ float g_v[RTOT*D];
// pre-split weights
__device__ __nv_bfloat16 g_Wkh[D*D],  g_Wkl[D*D];
__device__ __nv_bfloat16 g_Wvh[D*D],  g_Wvl[D*D];
__device__ __nv_bfloat16 g_Wqh[D*D],  g_Wql[D*D];
__device__ __nv_bfloat16 g_W1h[D*D],  g_W1l[D*D];
__device__ __nv_bfloat16 g_W2h[D*D],  g_W2l[D*D];
__device__ __nv_bfloat16 g_Wihh[3*D*D], g_Wihl[3*D*D];
__device__ __nv_bfloat16 g_Whhh[3*D*D], g_Whhl[3*D*D];
// loop state
__device__ float g_slots[MS*D];
__device__ float g_q[MS*D];
__device__ float g_attn[B*S*HW];
__device__ float g_upd[MS*D];
__device__ float g_h[MS*D];
__device__ float g_t[MS*D];

#define CLUSTER_SYNC() do { \
    __syncthreads(); \
    asm volatile("barrier.cluster.arrive.aligned;" ::: "memory"); \
    asm volatile("barrier.cluster.wait.aligned;"   ::: "memory"); \
} while (0)

// ---------------- helpers ----------------
__device__ __forceinline__ void bsplit(float x, __nv_bfloat16& h, __nv_bfloat16& l)
{
    h = __float2bfloat16(x);
    l = __float2bfloat16(x - __bfloat162float(h));
}

__device__ __forceinline__ void mma_bf16(float* d, const unsigned* a, const unsigned* b)
{
    asm volatile(
        "mma.sync.aligned.m16n8k16.row.col.f32.bf16.bf16.f32 "
        "{%0,%1,%2,%3}, {%4,%5,%6,%7}, {%8,%9}, {%0,%1,%2,%3};\n"
        : "+f"(d[0]), "+f"(d[1]), "+f"(d[2]), "+f"(d[3])
        : "r"(a[0]), "r"(a[1]), "r"(a[2]), "r"(a[3]), "r"(b[0]), "r"(b[1]));
}

__device__ __forceinline__ void cp16(unsigned dst, const void* src)
{
    asm volatile("cp.async.cg.shared.global [%0], [%1], 16;\n" :: "r"(dst), "l"(src));
}
#define CP_COMMIT() asm volatile("cp.async.commit_group;\n")
#define CP_WAIT1()  asm volatile("cp.async.wait_group 1;\n" ::: "memory")
#define CP_WAIT0()  asm volatile("cp.async.wait_group 0;\n" ::: "memory")

// ---------------- loop kernel shared-memory layout (dynamic) ----------------
#define AST 264     // bf16 stride of Ah/Al (32 rows)
#define WST 40      // bf16 stride of staged weights
#define QST 257     // fp32 stride of staged q
#define OST 97      // fp32 stride of sOut
#define WOFF 33792                        // bytes: after A region (2*32*264*2)
#define OOFF (WOFF + 30720)               // after W double-buffer (2*2*96*40*2)
#define LOOP_SMEM (OOFF + 24*OST*4)       // 73824 bytes

// ---- LN of 21 rows -> split bf16 staging (rows 21-23 zeroed) ----
__device__ __forceinline__ void ln_to_Abf(const float* __restrict__ src,
    const float* __restrict__ gam, const float* __restrict__ bet,
    __nv_bfloat16* Ah, __nv_bfloat16* Al, int w, int lane)
{
    __syncthreads();
    #pragma unroll
    for (int i = 0; i < 3; i++) {
        int r = w + 8*i;
        if (r < S) {
            float x[8]; float s = 0.f;
            #pragma unroll
            for (int c = 0; c < 8; c++) { x[c] = src[(size_t)r*256 + lane + 32*c]; s += x[c]; }
            #pragma unroll
            for (int o = 16; o; o >>= 1) s += __shfl_xor_sync(~0u, s, o);
            float mean = s * (1.f/256.f);
            float vs = 0.f;
            #pragma unroll
            for (int c = 0; c < 8; c++) { float d = x[c] - mean; vs += d*d; }
            #pragma unroll
            for (int o = 16; o; o >>= 1) vs += __shfl_xor_sync(~0u, vs, o);
            float inv = rsqrtf(vs * (1.f/256.f) + 1e-5f);
            #pragma unroll
            for (int c = 0; c < 8; c++) {
                int col = lane + 32*c;
                float y = (x[c]-mean)*inv*gam[col] + bet[col];
                __nv_bfloat16 h, l; bsplit(y, h, l);
                Ah[r*AST + col] = h; Al[r*AST + col] = l;
            }
        } else {
            #pragma unroll
            for (int c = 0; c < 8; c++) {
                int col = lane + 32*c;
                Ah[r*AST + col] = __float2bfloat16(0.f);
                Al[r*AST + col] = __float2bfloat16(0.f);
            }
        }
    }
    __syncthreads();
}

__device__ __forceinline__ void copy_to_Abf(const float* __restrict__ src,
    __nv_bfloat16* Ah, __nv_bfloat16* Al, int w, int lane)
{
    __syncthreads();
    #pragma unroll
    for (int i = 0; i < 3; i++) {
        int r = w + 8*i;
        #pragma unroll
        for (int c = 0; c < 8; c++) {
            int col = lane + 32*c;
            float y = (r < S) ? src[(size_t)r*256 + col] : 0.f;
            __nv_bfloat16 h, l; bsplit(y, h, l);
            Ah[r*AST + col] = h; Al[r*AST + col] = l;
        }
    }
    __syncthreads();
}

// ---- issue cp.async for one 32-k weight chunk (hi+lo) into buffer ----
template<int NG>
__device__ __forceinline__ void issue_w(const __nv_bfloat16* __restrict__ Wh_g,
    const __nv_bfloat16* __restrict__ Wl_g, const int* colb, int kt,
    unsigned wbase, int buf, int tid)
{
    const int half = 128*NG;
    #pragma unroll
    for (int l = 0; l < NG; l++) {
        int e = tid + l*256;
        int arr = (e < half) ? 0 : 1;
        int x = (e < half) ? e : e - half;
        int n = x >> 2, q = x & 3;
        int g = n >> 5, rn = n & 31;
        const __nv_bfloat16* src =
            (arr ? Wl_g : Wh_g) + (size_t)(colb[g] + rn)*256 + kt + q*8;
        unsigned dst = wbase + (unsigned)(buf*7680 + arr*3840 + n*WST + q*8)*2;
        cp16(dst, src);
    }
    CP_COMMIT();
}

// ---- D[24 x 32*NG] = A[24x256] @ Wslice^T via bf16x3 mma; result -> sOut ----
template<int NG>
__device__ __forceinline__ void small_gemm_bf(const __nv_bfloat16* __restrict__ Wh_g,
    const __nv_bfloat16* __restrict__ Wl_g, const int* colb,
    const __nv_bfloat16* Ah, const __nv_bfloat16* Al,
    __nv_bfloat16* Wsm, unsigned wbase, float* sOut,
    int tid, int w, int lane)
{
    float acc[NG][4];
    #pragma unroll
    for (int g = 0; g < NG; g++)
        #pragma unroll
        for (int j = 0; j < 4; j++) acc[g][j] = 0.f;

    int mt  = w >> 2;
    int ntb = (w & 3) * NG;
    int r = lane >> 2, c = lane & 3;
    int arow = mt*16 + r;

    issue_w<NG>(Wh_g, Wl_g, colb, 0, wbase, 0, tid);

    #pragma unroll
    for (int c8 = 0; c8 < 8; c8++) {
        if (c8 < 7) {
            issue_w<NG>(Wh_g, Wl_g, colb, (c8+1)*32, wbase, (c8+1)&1, tid);
            CP_WAIT1();
        } else {
            CP_WAIT0();
        }
        __syncthreads();
        const __nv_bfloat16* Wh_s = Wsm + (c8&1)*7680;
        const __nv_bfloat16* Wl_s = Wh_s + 3840;
        #pragma unroll
        for (int ks = 0; ks < 2; ks++) {
            int k0 = c8*32 + ks*16;   // offset in Ah (full-K staging)
            int kw = ks*16;           // offset in W chunk
            unsigned ah[4], al[4];
            {
                const __nv_bfloat16* p = Ah + arow*AST + k0 + 2*c;
                ah[0] = *(const unsigned*)p;
                ah[1] = *(const unsigned*)(p + 8*AST);
                ah[2] = *(const unsigned*)(p + 8);
                ah[3] = *(const unsigned*)(p + 8*AST + 8);
                const __nv_bfloat16* q = Al + arow*AST + k0 + 2*c;
                al[0] = *(const unsigned*)q;
                al[1] = *(const unsigned*)(q + 8*AST);
                al[2] = *(const unsigned*)(q + 8);
                al[3] = *(const unsigned*)(q + 8*AST + 8);
            }
            #pragma unroll
            for (int g = 0; g < NG; g++) {
                int n = (ntb + g)*8 + r;
                const __nv_bfloat16* ph = Wh_s + n*WST + kw + 2*c;
                unsigned bh[2] = { *(const unsigned*)ph, *(const unsigned*)(ph + 8) };
                const __nv_bfloat16* pl = Wl_s + n*WST + kw + 2*c;
                unsigned bl[2] = { *(const unsigned*)pl, *(const unsigned*)(pl + 8) };
                mma_bf16(acc[g], ah, bh);
                mma_bf16(acc[g], ah, bl);
                mma_bf16(acc[g], al, bh);
            }
        }
        __syncthreads();
    }
    #pragma unroll
    for (int g = 0; g < NG; g++) {
        int row0 = mt*16 + r;
        int cc = (ntb + g)*8 + 2*c;
        sOut[row0*OST + cc]     = acc[g][0];
        sOut[row0*OST + cc + 1] = acc[g][1];
        if (mt == 0) {
            sOut[(row0+8)*OST + cc]     = acc[g][2];
            sOut[(row0+8)*OST + cc + 1] = acc[g][3];
        }
    }
    __syncthreads();
}

// ---------------- persistent per-batch cluster kernel ----------------
__global__ void __cluster_dims__(RANKS, 1, 1) __launch_bounds__(256, 2)
slot_loop(
    const float* __restrict__ noise, const float* __restrict__ mu,
    const float* __restrict__ sg,
    const float* __restrict__ bq,  const float* __restrict__ b1,
    const float* __restrict__ b2,
    const float* __restrict__ bih, const float* __restrict__ bhh,
    const float* __restrict__ gsl, const float* __restrict__ besl,
    const float* __restrict__ gff, const float* __restrict__ beff,
    float* __restrict__ out, float* __restrict__ out_attn)
{
    extern __shared__ char sm[];
    __nv_bfloat16* Ah = (__nv_bfloat16*)sm;
    __nv_bfloat16* Al = Ah + 32*AST;
    float* sQ   = (float*)sm;                 // alias A region
    float* sAtt = (float*)sm;                 // alias A region
    __nv_bfloat16* Wsm = (__nv_bfloat16*)(sm + WOFF);
    float* sV   = (float*)(sm + WOFF);        // alias W region (96 x 33 fp32)
    float* sOut = (float*)(sm + OOFF);
    unsigned wbase = (unsigned)__cvta_generic_to_shared(Wsm);

    int tid  = threadIdx.x;
    int w    = tid >> 5, lane = tid & 31;
    int rank = blockIdx.x;
    int b    = blockIdx.y;
    int colq = 32*rank;
    int col  = colq + lane;
    int colb1[1] = { colq };
    int colb3[3] = { colq, 256 + colq, 512 + colq };

    float* slots_b = g_slots + (size_t)b*S*256;
    float* q_b     = g_q     + (size_t)b*S*256;
    float* upd_b   = g_upd   + (size_t)b*S*256;
    float* h_b     = g_h     + (size_t)b*S*256;
    float* t_b     = g_t     + (size_t)b*S*256;
    float* attn_b  = g_attn  + (size_t)b*S*HW;

    // slots0 = mu + sigma*noise
    #pragma unroll
    for (int i = 0; i < 3; i++) {
        int r = w + 8*i;
        if (r < S)
            slots_b[(size_t)r*256 + col] = mu[col] + sg[col]*noise[(size_t)(b*S + r)*256 + col];
    }
    CLUSTER_SYNC();

    float gh[3][3];
    float hreg[3];

    for (int f = 0; f < NF; f++) {
        for (int it = 0; it < 3; it++) {
            // ---- S1: q = LN_sl(slots) @ Wq^T + bq ----
            ln_to_Abf(slots_b, gsl, besl, Ah, Al, w, lane);
            small_gemm_bf<1>(g_Wqh, g_Wql, colb1, Ah, Al, Wsm, wbase, sOut, tid, w, lane);
            #pragma unroll
            for (int i = 0; i < 3; i++) {
                int r = w + 8*i;
                if (r < S) q_b[(size_t)r*256 + col] = sOut[r*OST + lane] + bq[col];
            }
            CLUSTER_SYNC();

            // ---- S2: dots+softmax (24 j's per rank) ; gh GEMM ----
            __syncthreads();
            #pragma unroll
            for (int i = 0; i < 3; i++) {
                int r = w + 8*i;
                if (r < S)
                    #pragma unroll
                    for (int c = 0; c < 8; c++)
                        sQ[r*QST + lane + 32*c] = q_b[(size_t)r*256 + lane + 32*c];
            }
            __syncthreads();
            #pragma unroll
            for (int jj = 0; jj < 3; jj++) {
                int j = 24*rank + w*3 + jj;
                const float* kr = g_k + ((size_t)(b*NF + f)*HW + j)*256;
                float kv[8];
                #pragma unroll
                for (int c = 0; c < 8; c++) kv[c] = kr[lane + 32*c];
                float myd = 0.f;
                #pragma unroll
                for (int i = 0; i < S; i++) {
                    float p = 0.f;
                    #pragma unroll
                    for (int c = 0; c < 8; c++)
                        p = fmaf(sQ[i*QST + lane + 32*c], kv[c], p);
                    #pragma unroll
                    for (int o = 16; o; o >>= 1) p += __shfl_xor_sync(~0u, p, o);
                    if (lane == i) myd = p;
                }
                float x = (lane < S) ? myd * 0.0625f : -1e30f;
                float mx = x;
                #pragma unroll
                for (int o = 16; o; o >>= 1) mx = fmaxf(mx, __shfl_xor_sync(~0u, mx, o));
                float e = (lane < S) ? expf(x - mx) : 0.f;
                float sum = e;
                #pragma unroll
                for (int o = 16; o; o >>= 1) sum += __shfl_xor_sync(~0u, sum, o);
                float a = e / sum + 1e-8f;
                if (lane < S) {
                    attn_b[(size_t)lane*HW + j] = a;
                    if (it == 2)
                        out_attn[(size_t)((b*NF + f)*S + lane)*HW + j] = a;
                }
            }
            // gh = slots @ Whh^T at gate cols {c, 256+c, 512+c}
            copy_to_Abf(slots_b, Ah, Al, w, lane);
            small_gemm_bf<3>(g_Whhh, g_Whhl, colb3, Ah, Al, Wsm, wbase, sOut, tid, w, lane);
            #pragma unroll
            for (int i = 0; i < 3; i++) {
                int r = w + 8*i;
                #pragma unroll
                for (int g = 0; g < 3; g++)
                    gh[i][g] = (r < S) ? sOut[r*OST + g*32 + lane] : 0.f;
            }
            CLUSTER_SYNC();

            // ---- S3: updates = (attn/rowsum) @ v ----
            __syncthreads();
            for (int l = 0; l < 16; l++) {
                int e = tid + l*256;
                if (e < S*HW) sAtt[e] = attn_b[e];
            }
            __syncthreads();
            float rsv[3];
            #pragma unroll
            for (int i = 0; i < 3; i++) {
                int r = w + 8*i;
                if (r < S) {
                    float s = 0.f;
                    #pragma unroll
                    for (int c = 0; c < 6; c++) s += sAtt[r*HW + lane + 32*c];
                    #pragma unroll
                    for (int o = 16; o; o >>= 1) s += __shfl_xor_sync(~0u, s, o);
                    rsv[i] = s;
                }
            }
            float ua[3] = {0.f, 0.f, 0.f};
            int r0 = w, r1 = w + 8, r2 = w + 16;
            for (int half = 0; half < 2; half++) {
                __syncthreads();
                #pragma unroll
                for (int l = 0; l < 12; l++) {
                    int e = tid + l*256;
                    int jl = e >> 5, cl = e & 31;
                    sV[jl*33 + cl] =
                        g_v[((size_t)(b*NF + f)*HW + half*96 + jl)*256 + colq + cl];
                }
                __syncthreads();
                #pragma unroll 4
                for (int j = 0; j < 96; j++) {
                    float vv = sV[j*33 + lane];
                    ua[0] = fmaf(sAtt[r0*HW + half*96 + j], vv, ua[0]);
                    ua[1] = fmaf(sAtt[r1*HW + half*96 + j], vv, ua[1]);
                    if (r2 < S) ua[2] = fmaf(sAtt[r2*HW + half*96 + j], vv, ua[2]);
                }
            }
            __syncthreads();
            #pragma unroll
            for (int i = 0; i < 3; i++) {
                int r = w + 8*i;
                if (r < S) upd_b[(size_t)r*256 + col] = ua[i] / rsv[i];
            }
            CLUSTER_SYNC();

            // ---- S4: gi GEMM + GRU combine -> h ----
            copy_to_Abf(upd_b, Ah, Al, w, lane);
            small_gemm_bf<3>(g_Wihh, g_Wihl, colb3, Ah, Al, Wsm, wbase, sOut, tid, w, lane);
            #pragma unroll
            for (int i = 0; i < 3; i++) {
                int r = w + 8*i;
                if (r < S) {
                    float irv = sOut[r*OST + lane]      + bih[col];
                    float izv = sOut[r*OST + 32 + lane] + bih[256 + col];
                    float inv = sOut[r*OST + 64 + lane] + bih[512 + col];
                    float hrv = gh[i][0] + bhh[col];
                    float hzv = gh[i][1] + bhh[256 + col];
                    float hnv = gh[i][2] + bhh[512 + col];
                    float rr = 1.f / (1.f + expf(-(irv + hrv)));
                    float zz = 1.f / (1.f + expf(-(izv + hzv)));
                    float nn = tanhf(inv + rr*hnv);
                    float sl = slots_b[(size_t)r*256 + col];
                    float hv = (1.f - zz)*nn + zz*sl;
                    hreg[i] = hv;
                    h_b[(size_t)r*256 + col] = hv;
                }
            }
            CLUSTER_SYNC();

            // ---- S5: t = relu(LN_ff(h) @ W1^T + b1) ----
            ln_to_Abf(h_b, gff, beff, Ah, Al, w, lane);
            small_gemm_bf<1>(g_W1h, g_W1l, colb1, Ah, Al, Wsm, wbase, sOut, tid, w, lane);
            #pragma unroll
            for (int i = 0; i < 3; i++) {
                int r = w + 8*i;
                if (r < S) t_b[(size_t)r*256 + col] = fmaxf(sOut[r*OST + lane] + b1[col], 0.f);
            }
            CLUSTER_SYNC();

            // ---- S6: slots = t @ W2^T + b2 + h ----
            copy_to_Abf(t_b, Ah, Al, w, lane);
            small_gemm_bf<1>(g_W2h, g_W2l, colb1, Ah, Al, Wsm, wbase, sOut, tid, w, lane);
            #pragma unroll
            for (int i = 0; i < 3; i++) {
                int r = w + 8*i;
                if (r < S) slots_b[(size_t)r*256 + col] = sOut[r*OST + lane] + b2[col] + hreg[i];
            }
            CLUSTER_SYNC();
        }
    }

    #pragma unroll
    for (int i = 0; i < 3; i++) {
        int r = w + 8*i;
        if (r < NA)
            out[(size_t)(b*NA + r)*256 + col] = slots_b[(size_t)r*256 + col];
    }
}

// ---------------- prepass: fused k+v GEMM, pre-split operands, cp.async ----
// grid (4, 768): which = bx>>1, n0 = (bx&1)*128 ; CTA tile 128m x 128n, K=256.
#define KVA 5120     // elems per staged array (128 x 40)
#define KVB 20480    // elems per buffer (4 arrays)
__global__ void __launch_bounds__(256) kv_gemm(
    const float* __restrict__ bk, float* __restrict__ Ck,
    const float* __restrict__ bv, float* __restrict__ Cv)
{
    extern __shared__ __nv_bfloat16 smkv[];
    unsigned sbase = (unsigned)__cvta_generic_to_shared(smkv);

    int m0 = blockIdx.y * 128;
    int which = blockIdx.x >> 1;
    int n0 = (blockIdx.x & 1) * 128;
    const __nv_bfloat16* Wh_g = which ? g_Wvh : g_Wkh;
    const __nv_bfloat16* Wl_g = which ? g_Wvl : g_Wkl;
    const float* bias = which ? bv : bk;
    float* C          = which ? Cv : Ck;

    int tid = threadIdx.x;
    int w = tid >> 5, lane = tid & 31;
    int wm = w >> 1, wn = w & 1;
    int r = lane >> 2, c = lane & 3;

    float acc[2][8][4];
    #pragma unroll
    for (int mt = 0; mt < 2; mt++)
        #pragma unroll
        for (int nt = 0; nt < 8; nt++)
            #pragma unroll
            for (int j = 0; j < 4; j++) acc[mt][nt][j] = 0.f;

    // issue one 32-k chunk: 4 arrays (Ah, Al, Wh, Wl) x 128 rows x 32 k
    auto issue = [&](int kt, int buf) {
        #pragma unroll
        for (int l = 0; l < 8; l++) {
            int e = tid + l*256;
            int arr = e >> 9, x = e & 511;
            int row = x >> 2, q = x & 3;
            const __nv_bfloat16* src;
            switch (arr) {
                case 0: src = g_Ah + (size_t)(m0 + row)*256 + kt + q*8; break;
                case 1: src = g_Al + (size_t)(m0 + row)*256 + kt + q*8; break;
                case 2: src = Wh_g + (size_t)(n0 + row)*256 + kt + q*8; break;
                default:src = Wl_g + (size_t)(n0 + row)*256 + kt + q*8; break;
            }
            unsigned dst = sbase + (unsigned)(buf*KVB + arr*KVA + row*40 + q*8)*2;
            cp16(dst, src);
        }
        CP_COMMIT();
    };

    issue(0, 0);
    #pragma unroll
    for (int c8 = 0; c8 < 8; c8++) {
        if (c8 < 7) { issue((c8+1)*32, (c8+1)&1); CP_WAIT1(); }
        else        { CP_WAIT0(); }
        __syncthreads();
        const __nv_bfloat16* sAh = smkv + (c8&1)*KVB;
        const __nv_bfloat16* sAl = sAh + KVA;
        const __nv_bfloat16* sWh = sAh + 2*KVA;
        const __nv_bfloat16* sWl = sAh + 3*KVA;
        #pragma unroll
        for (int ks = 0; ks < 2; ks++) {
            int k0 = ks*16;
            unsigned ah[2][4], al[2][4];
            #pragma unroll
            for (int mt = 0; mt < 2; mt++) {
                int row = wm*32 + mt*16 + r;
                const __nv_bfloat16* p = sAh + row*40 + k0 + 2*c;
                ah[mt][0] = *(const unsigned*)p;
                ah[mt][1] = *(const unsigned*)(p + 8*40);
                ah[mt][2] = *(const unsigned*)(p + 8);
                ah[mt][3] = *(const unsigned*)(p + 8*40 + 8);
                const __nv_bfloat16* q = sAl + row*40 + k0 + 2*c;
                al[mt][0] = *(const unsigned*)q;
                al[mt][1] = *(const unsigned*)(q + 8*40);
                al[mt][2] = *(const unsigned*)(q + 8);
                al[mt][3] = *(const unsigned*)(q + 8*40 + 8);
            }
            #pragma unroll
            for (int nt = 0; nt < 8; nt++) {
                int n = wn*64 + nt*8 + r;
                const __nv_bfloat16* ph = sWh + n*40 + k0 + 2*c;
                unsigned bh[2] = { *(const unsigned*)ph, *(const unsigned*)(ph + 8) };
                const __nv_bfloat16* pl = sWl + n*40 + k0 + 2*c;
                unsigned bl[2] = { *(const unsigned*)pl, *(const unsigned*)(pl + 8) };
                #pragma unroll
                for (int mt = 0; mt < 2; mt++) {
                    mma_bf16(acc[mt][nt], ah[mt], bh);
                    mma_bf16(acc[mt][nt], ah[mt], bl);
                    mma_bf16(acc[mt][nt], al[mt], bh);
                }
            }
        }
        __syncthreads();
    }
    #pragma unroll
    for (int mt = 0; mt < 2; mt++)
        #pragma unroll
        for (int nt = 0; nt < 8; nt++) {
            int row = m0 + wm*32 + mt*16 + r;
            int cc = n0 + wn*64 + nt*8 + 2*c;
            float b0 = bias[cc], b1 = bias[cc+1];
            C[(size_t)row*256 + cc]       = acc[mt][nt][0] + b0;
            C[(size_t)row*256 + cc + 1]   = acc[mt][nt][1] + b1;
            C[(size_t)(row+8)*256 + cc]   = acc[mt][nt][2] + b0;
            C[(size_t)(row+8)*256 + cc+1] = acc[mt][nt][3] + b1;
        }
}

// ---------------- input LayerNorm: warp per row, emit split bf16 ----------
__global__ void __launch_bounds__(256) ln_kernel(const float* __restrict__ X,
    const float* __restrict__ g, const float* __restrict__ be)
{
    int w = threadIdx.x >> 5, lane = threadIdx.x & 31;
    size_t row = (size_t)blockIdx.x*8 + w;
    const float* Xr = X + row*256;
    float x[8]; float s = 0.f;
    #pragma unroll
    for (int c = 0; c < 8; c++) { x[c] = Xr[lane + 32*c]; s += x[c]; }
    #pragma unroll
    for (int o = 16; o; o >>= 1) s += __shfl_xor_sync(~0u, s, o);
    float mean = s * (1.f/256.f);
    float vs = 0.f;
    #pragma unroll
    for (int c = 0; c < 8; c++) { float d = x[c] - mean; vs += d*d; }
    #pragma unroll
    for (int o = 16; o; o >>= 1) vs += __shfl_xor_sync(~0u, vs, o);
    float inv = rsqrtf(vs * (1.f/256.f) + 1e-5f);
    #pragma unroll
    for (int c = 0; c < 8; c++) {
        int col = lane + 32*c;
        float y = (x[c]-mean)*inv*g[col] + be[col];
        __nv_bfloat16 h, l; bsplit(y, h, l);
        g_Ah[row*256 + col] = h;
        g_Al[row*256 + col] = l;
    }
}

// ---------------- weight split conversion ----------------
__global__ void conv_split(const float* __restrict__ W,
    __nv_bfloat16* __restrict__ Hp, __nv_bfloat16* __restrict__ Lp, int n)
{
    int i = blockIdx.x*256 + threadIdx.x;
    if (i < n) {
        __nv_bfloat16 h, l; bsplit(W[i], h, l);
        Hp[i] = h; Lp[i] = l;
    }
}

// ---------------- host orchestration ----------------
extern "C" void kernel_launch(void* const* d_in, const int* in_sizes, int n_in,
                              void* d_out, int out_size)
{
    const float* inputs = (const float*)d_in[0];
    const float* noise  = (const float*)d_in[1];
    const float* mu     = (const float*)d_in[2];
    const float* sigma  = (const float*)d_in[3];
    const float* Wq  = (const float*)d_in[4];  const float* bq  = (const float*)d_in[5];
    const float* Wk  = (const float*)d_in[6];  const float* bk  = (const float*)d_in[7];
    const float* Wv  = (const float*)d_in[8];  const float* bv  = (const float*)d_in[9];
    const float* W1  = (const float*)d_in[10]; const float* b1  = (const float*)d_in[11];
    const float* W2  = (const float*)d_in[12]; const float* b2  = (const float*)d_in[13];
    const float* Wih = (const float*)d_in[14]; const float* bih = (const float*)d_in[15];
    const float* Whh = (const float*)d_in[16]; const float* bhh = (const float*)d_in[17];
    const float* gin = (const float*)d_in[18]; const float* bein = (const float*)d_in[19];
    const float* gsl = (const float*)d_in[20]; const float* besl = (const float*)d_in[21];
    const float* gff = (const float*)d_in[22]; const float* beff = (const float*)d_in[23];

    float* out = (float*)d_out;
    float* out_attn = out + (size_t)B*NA*D;

    float *kbuf, *vbuf;
    cudaGetSymbolAddress((void**)&kbuf, g_k);
    cudaGetSymbolAddress((void**)&vbuf, g_v);
    __nv_bfloat16 *wkh,*wkl,*wvh,*wvl,*wqh,*wql,*w1h,*w1l,*w2h,*w2l,*wihh,*wihl,*whhh,*whhl;
    cudaGetSymbolAddress((void**)&wkh, g_Wkh);  cudaGetSymbolAddress((void**)&wkl, g_Wkl);
    cudaGetSymbolAddress((void**)&wvh, g_Wvh);  cudaGetSymbolAddress((void**)&wvl, g_Wvl);
    cudaGetSymbolAddress((void**)&wqh, g_Wqh);  cudaGetSymbolAddress((void**)&wql, g_Wql);
    cudaGetSymbolAddress((void**)&w1h, g_W1h);  cudaGetSymbolAddress((void**)&w1l, g_W1l);
    cudaGetSymbolAddress((void**)&w2h, g_W2h);  cudaGetSymbolAddress((void**)&w2l, g_W2l);
    cudaGetSymbolAddress((void**)&wihh, g_Wihh); cudaGetSymbolAddress((void**)&wihl, g_Wihl);
    cudaGetSymbolAddress((void**)&whhh, g_Whhh); cudaGetSymbolAddress((void**)&whhl, g_Whhl);

    cudaFuncSetAttribute(slot_loop, cudaFuncAttributeMaxDynamicSharedMemorySize, LOOP_SMEM);
    cudaFuncSetAttribute(kv_gemm,   cudaFuncAttributeMaxDynamicSharedMemorySize, 2*KVB*2);

    // weight splits (tiny)
    conv_split<<<256, 256>>>(Wk,  wkh,  wkl,  D*D);
    conv_split<<<256, 256>>>(Wv,  wvh,  wvl,  D*D);
    conv_split<<<256, 256>>>(Wq,  wqh,  wql,  D*D);
    conv_split<<<256, 256>>>(W1,  w1h,  w1l,  D*D);
    conv_split<<<256, 256>>>(W2,  w2h,  w2l,  D*D);
    conv_split<<<768, 256>>>(Wih, wihh, wihl, 3*D*D);
    conv_split<<<768, 256>>>(Whh, whhh, whhl, 3*D*D);

    // LN all input rows -> split bf16 A
    ln_kernel<<<RTOT/8, 256>>>(inputs, gin, bein);

    // k & v for all frames
    kv_gemm<<<dim3(4, RTOT/128), 256, 2*KVB*2>>>(bk, kbuf, bv, vbuf);

    // sequential part: one 8-CTA cluster per batch
    slot_loop<<<dim3(RANKS, B), 256, LOOP_SMEM>>>(
        noise, mu, sigma, bq, b1, b2, bih, bhh,
        gsl, besl, gff, beff, out, out_attn);
}